// round 1
// baseline (speedup 1.0000x reference)
#include <cuda_runtime.h>
#include <cstddef>

#define DIM 1024
#define NH 16
#define HD 64
#define NB 8
#define LQ 512
#define LKK 1024
#define MQ (NB*LQ)      // 4096
#define MK (NB*LKK)     // 8192
#define EPSV 1e-5f
#define QSCALE 0.125f   // 1/sqrt(64)

typedef unsigned long long ull;

// ------------------------- scratch (static device globals) -------------------------
__device__ float g_Q[(size_t)MQ * DIM];        // 16 MB
__device__ float g_KV[(size_t)MK * 2 * DIM];   // 64 MB  (K cols 0..1023, V cols 1024..2047)
__device__ float g_ctx[(size_t)MQ * DIM];      // 16 MB
__device__ float g_att[(size_t)MQ * DIM];      // 16 MB

// ------------------------- packed f32x2 helpers -------------------------
__device__ __forceinline__ ull pack2(float lo, float hi) {
    ull r; asm("mov.b64 %0, {%1, %2};" : "=l"(r) : "f"(lo), "f"(hi)); return r;
}
__device__ __forceinline__ void fma2(ull& d, ull a, ull b) {
    asm("fma.rn.f32x2 %0, %1, %2, %3;" : "=l"(d) : "l"(a), "l"(b), "l"(d));
}
__device__ __forceinline__ float2 unpack2(ull v) {
    float2 r; asm("mov.b64 {%0, %1}, %2;" : "=f"(r.x), "=f"(r.y) : "l"(v)); return r;
}

// ------------------------- SGEMM: C[M,N] = A[M,K] @ W[N,K]^T + bias (+res) -------------------------
#define BM 128
#define BN 128
#define BK 16

__global__ __launch_bounds__(256, 2) void sgemm_bias(
    const float* __restrict__ A, const float* __restrict__ W,
    const float* __restrict__ bias, const float* __restrict__ res,
    float* __restrict__ C, int M, int N, int K)
{
    __shared__ float As[BK][BM];
    __shared__ float Ws[BK][BN];

    const int tid = threadIdx.x;
    const int bm = blockIdx.y * BM;
    const int bn = blockIdx.x * BN;
    const int m_off = (tid >> 4) << 3;
    const int n_off = (tid & 15) << 3;

    ull acc[8][4];
#pragma unroll
    for (int i = 0; i < 8; i++)
#pragma unroll
        for (int j = 0; j < 4; j++) acc[i][j] = 0ULL;

    const int lrow = tid >> 2;            // 0..63
    const int lkq  = (tid & 3) << 2;      // 0,4,8,12
    const float* Ap = A + (size_t)(bm + lrow) * K + lkq;
    const float* Wp = W + (size_t)(bn + lrow) * K + lkq;
    const size_t half = (size_t)64 * K;

    for (int k0 = 0; k0 < K; k0 += BK) {
        float4 a0 = *(const float4*)(Ap + k0);
        float4 a1 = *(const float4*)(Ap + half + k0);
        float4 w0 = *(const float4*)(Wp + k0);
        float4 w1 = *(const float4*)(Wp + half + k0);
        __syncthreads();
        As[lkq+0][lrow] = a0.x; As[lkq+1][lrow] = a0.y; As[lkq+2][lrow] = a0.z; As[lkq+3][lrow] = a0.w;
        As[lkq+0][lrow+64] = a1.x; As[lkq+1][lrow+64] = a1.y; As[lkq+2][lrow+64] = a1.z; As[lkq+3][lrow+64] = a1.w;
        Ws[lkq+0][lrow] = w0.x; Ws[lkq+1][lrow] = w0.y; Ws[lkq+2][lrow] = w0.z; Ws[lkq+3][lrow] = w0.w;
        Ws[lkq+0][lrow+64] = w1.x; Ws[lkq+1][lrow+64] = w1.y; Ws[lkq+2][lrow+64] = w1.z; Ws[lkq+3][lrow+64] = w1.w;
        __syncthreads();
#pragma unroll
        for (int kk = 0; kk < BK; kk++) {
            float4 av0 = *(const float4*)&As[kk][m_off];
            float4 av1 = *(const float4*)&As[kk][m_off + 4];
            float4 bv0 = *(const float4*)&Ws[kk][n_off];
            float4 bv1 = *(const float4*)&Ws[kk][n_off + 4];
            ull b01 = pack2(bv0.x, bv0.y);
            ull b23 = pack2(bv0.z, bv0.w);
            ull b45 = pack2(bv1.x, bv1.y);
            ull b67 = pack2(bv1.z, bv1.w);
            float am[8] = {av0.x, av0.y, av0.z, av0.w, av1.x, av1.y, av1.z, av1.w};
#pragma unroll
            for (int i = 0; i < 8; i++) {
                ull ad = pack2(am[i], am[i]);
                fma2(acc[i][0], ad, b01);
                fma2(acc[i][1], ad, b23);
                fma2(acc[i][2], ad, b45);
                fma2(acc[i][3], ad, b67);
            }
        }
    }

#pragma unroll
    for (int i = 0; i < 8; i++) {
        const int m = bm + m_off + i;
        float2 c0 = unpack2(acc[i][0]);
        float2 c1 = unpack2(acc[i][1]);
        float2 c2 = unpack2(acc[i][2]);
        float2 c3 = unpack2(acc[i][3]);
        float o8[8] = {c0.x, c0.y, c1.x, c1.y, c2.x, c2.y, c3.x, c3.y};
#pragma unroll
        for (int j = 0; j < 8; j++) o8[j] += bias[bn + n_off + j];
        const size_t base = (size_t)m * N + bn + n_off;
        if (res) {
            float4 r0 = *(const float4*)&res[base];
            float4 r1 = *(const float4*)&res[base + 4];
            o8[0] += r0.x; o8[1] += r0.y; o8[2] += r0.z; o8[3] += r0.w;
            o8[4] += r1.x; o8[5] += r1.y; o8[6] += r1.z; o8[7] += r1.w;
        }
        *(float4*)&C[base]     = make_float4(o8[0], o8[1], o8[2], o8[3]);
        *(float4*)&C[base + 4] = make_float4(o8[4], o8[5], o8[6], o8[7]);
    }
}

// ------------------------- fused attention -------------------------
// block = (batch b, 32-query tile). Loops all 16 heads -> attn_weights rmw without atomics.
// smem: S[32][1024] fp32 scores/probs, Qs[32][64], KT[64][68] (K^T), Vs[64][64]
#define ATTN_SMEM ((32*LKK + 32*HD + HD*68 + 64*HD) * 4)

__global__ __launch_bounds__(256) void attn_kernel(float* __restrict__ attnw)
{
    extern __shared__ float sm[];
    float* S  = sm;                   // 32*1024
    float* Qs = sm + 32 * LKK;        // 32*64
    float* KT = Qs + 32 * HD;         // 64*68
    float* Vs = KT + HD * 68;         // 64*64

    const int tid = threadIdx.x;
    const int b  = blockIdx.x >> 4;
    const int q0 = (blockIdx.x & 15) << 5;
    const int tq = tid >> 4;      // 0..15 -> query pair
    const int tk = tid & 15;      // 0..15 -> key/dim quad

    for (int h = 0; h < NH; h++) {
        // ---- load Q tile (pre-scaled) ----
#pragma unroll
        for (int i = 0; i < 2; i++) {
            int f = tid + i * 256;
            int q = f >> 4;
            int d4 = (f & 15) << 2;
            float4 v = *(const float4*)&g_Q[((size_t)(b * LQ + q0 + q)) * DIM + h * HD + d4];
            v.x *= QSCALE; v.y *= QSCALE; v.z *= QSCALE; v.w *= QSCALE;
            *(float4*)&Qs[q * HD + d4] = v;
        }
        // ---- scores S = Qs @ K^T ----
        for (int kc = 0; kc < LKK / 64; kc++) {
            __syncthreads();
#pragma unroll
            for (int i = 0; i < 4; i++) {
                int f = tid + i * 256;
                int kk = f >> 4;
                int d4 = (f & 15) << 2;
                float4 v = *(const float4*)&g_KV[((size_t)(b * LKK + kc * 64 + kk)) * (2 * DIM) + h * HD + d4];
                KT[(d4 + 0) * 68 + kk] = v.x;
                KT[(d4 + 1) * 68 + kk] = v.y;
                KT[(d4 + 2) * 68 + kk] = v.z;
                KT[(d4 + 3) * 68 + kk] = v.w;
            }
            __syncthreads();
            ull a00 = 0, a01 = 0, a10 = 0, a11 = 0;
            const float* qp0 = &Qs[(2 * tq) * HD];
            const float* qp1 = &Qs[(2 * tq + 1) * HD];
#pragma unroll 8
            for (int d = 0; d < HD; d++) {
                float qa = qp0[d], qb = qp1[d];
                float4 kv = *(const float4*)&KT[d * 68 + 4 * tk];
                ull qa2 = pack2(qa, qa), qb2 = pack2(qb, qb);
                ull k01 = pack2(kv.x, kv.y), k23 = pack2(kv.z, kv.w);
                fma2(a00, qa2, k01); fma2(a01, qa2, k23);
                fma2(a10, qb2, k01); fma2(a11, qb2, k23);
            }
            float2 r0 = unpack2(a00), r1 = unpack2(a01);
            *(float4*)&S[(2 * tq) * LKK + kc * 64 + 4 * tk] = make_float4(r0.x, r0.y, r1.x, r1.y);
            r0 = unpack2(a10); r1 = unpack2(a11);
            *(float4*)&S[(2 * tq + 1) * LKK + kc * 64 + 4 * tk] = make_float4(r0.x, r0.y, r1.x, r1.y);
        }
        __syncthreads();
        // ---- softmax over rows (8 warps x 4 rows) ----
        {
            const int w = tid >> 5, lane = tid & 31;
            for (int r = w * 4; r < w * 4 + 4; r++) {
                float* row = &S[r * LKK];
                float mx = -1e30f;
#pragma unroll
                for (int j = 0; j < LKK / 32; j++) mx = fmaxf(mx, row[j * 32 + lane]);
#pragma unroll
                for (int o = 16; o > 0; o >>= 1) mx = fmaxf(mx, __shfl_xor_sync(0xffffffffu, mx, o));
                float s = 0.f;
#pragma unroll
                for (int j = 0; j < LKK / 32; j++) {
                    float e = __expf(row[j * 32 + lane] - mx);
                    row[j * 32 + lane] = e;
                    s += e;
                }
#pragma unroll
                for (int o = 16; o > 0; o >>= 1) s += __shfl_xor_sync(0xffffffffu, s, o);
                float inv = 1.0f / s;
#pragma unroll
                for (int j = 0; j < LKK / 32; j++) row[j * 32 + lane] *= inv;
            }
        }
        __syncthreads();
        // ---- attn_weights accumulation (mean over heads) ----
        {
            float4* aw4 = (float4*)(attnw + ((size_t)(b * LQ + q0)) * LKK);
            const float4* S4 = (const float4*)S;
            const float invh = 1.0f / NH;
            if (h == 0) {
                for (int f = tid; f < 32 * LKK / 4; f += 256) {
                    float4 p = S4[f];
                    p.x *= invh; p.y *= invh; p.z *= invh; p.w *= invh;
                    aw4[f] = p;
                }
            } else {
                for (int f = tid; f < 32 * LKK / 4; f += 256) {
                    float4 p = S4[f];
                    float4 o = aw4[f];
                    o.x += p.x * invh; o.y += p.y * invh; o.z += p.z * invh; o.w += p.w * invh;
                    aw4[f] = o;
                }
            }
        }
        // ---- ctx = P @ V ----
        ull c00 = 0, c01 = 0, c10 = 0, c11 = 0;
        for (int kc = 0; kc < LKK / 64; kc++) {
            __syncthreads();
#pragma unroll
            for (int i = 0; i < 4; i++) {
                int f = tid + i * 256;
                int kk = f >> 4;
                int d4 = (f & 15) << 2;
                float4 v = *(const float4*)&g_KV[((size_t)(b * LKK + kc * 64 + kk)) * (2 * DIM) + DIM + h * HD + d4];
                *(float4*)&Vs[kk * HD + d4] = v;
            }
            __syncthreads();
            const float* p0 = &S[(2 * tq) * LKK + kc * 64];
            const float* p1 = &S[(2 * tq + 1) * LKK + kc * 64];
#pragma unroll 8
            for (int kk = 0; kk < 64; kk++) {
                float pa = p0[kk], pb = p1[kk];
                float4 vv = *(const float4*)&Vs[kk * HD + 4 * tk];
                ull pa2 = pack2(pa, pa), pb2 = pack2(pb, pb);
                ull v01 = pack2(vv.x, vv.y), v23 = pack2(vv.z, vv.w);
                fma2(c00, pa2, v01); fma2(c01, pa2, v23);
                fma2(c10, pb2, v01); fma2(c11, pb2, v23);
            }
        }
        {
            float2 r0 = unpack2(c00), r1 = unpack2(c01);
            *(float4*)&g_ctx[((size_t)(b * LQ + q0 + 2 * tq)) * DIM + h * HD + 4 * tk] =
                make_float4(r0.x, r0.y, r1.x, r1.y);
            r0 = unpack2(c10); r1 = unpack2(c11);
            *(float4*)&g_ctx[((size_t)(b * LQ + q0 + 2 * tq + 1)) * DIM + h * HD + 4 * tk] =
                make_float4(r0.x, r0.y, r1.x, r1.y);
        }
        // next head's first __syncthreads (score loop) gates smem reuse of S/KT/Vs;
        // Qs reload only conflicts with score-phase reads, which are already done.
    }
}

// ------------------------- layernorm (+ already-added residual input) -------------------------
__global__ __launch_bounds__(256) void ln_kernel(
    const float* __restrict__ X, const float* __restrict__ gam,
    const float* __restrict__ bet, float* __restrict__ out)
{
    __shared__ float red[64];
    __shared__ float s_mu, s_rinv;
    const int r = blockIdx.x, tid = threadIdx.x;
    const float* x = X + (size_t)r * DIM;
    float4 v = *(const float4*)&x[tid * 4];
    float s  = v.x + v.y + v.z + v.w;
    float sq = v.x * v.x + v.y * v.y + v.z * v.z + v.w * v.w;
#pragma unroll
    for (int o = 16; o > 0; o >>= 1) {
        s  += __shfl_xor_sync(0xffffffffu, s, o);
        sq += __shfl_xor_sync(0xffffffffu, sq, o);
    }
    const int w = tid >> 5;
    if ((tid & 31) == 0) { red[w] = s; red[32 + w] = sq; }
    __syncthreads();
    if (tid == 0) {
        float S = 0, Q = 0;
        for (int i = 0; i < 8; i++) { S += red[i]; Q += red[32 + i]; }
        float mu = S * (1.0f / DIM);
        float var = Q * (1.0f / DIM) - mu * mu;
        s_mu = mu;
        s_rinv = rsqrtf(var + EPSV);
    }
    __syncthreads();
    const float mu = s_mu, rinv = s_rinv;
    float4 gg = *(const float4*)&gam[tid * 4];
    float4 bb = *(const float4*)&bet[tid * 4];
    float4 o;
    o.x = (v.x - mu) * rinv * gg.x + bb.x;
    o.y = (v.y - mu) * rinv * gg.y + bb.y;
    o.z = (v.z - mu) * rinv * gg.z + bb.z;
    o.w = (v.w - mu) * rinv * gg.w + bb.w;
    *(float4*)&out[(size_t)r * DIM + tid * 4] = o;
}

// ------------------------- launch -------------------------
extern "C" void kernel_launch(void* const* d_in, const int* in_sizes, int n_in,
                              void* d_out, int out_size)
{
    const float* text   = (const float*)d_in[0];
    const float* vision = (const float*)d_in[1];
    const float* ipw    = (const float*)d_in[2];
    const float* ipb    = (const float*)d_in[3];
    const float* outw   = (const float*)d_in[4];
    const float* outb   = (const float*)d_in[5];
    const float* lng    = (const float*)d_in[6];
    const float* lnb    = (const float*)d_in[7];

    float* out   = (float*)d_out;
    float* attnw = out + (size_t)MQ * DIM;

    float *Qp, *KVp, *ctxp, *attp;
    cudaGetSymbolAddress((void**)&Qp, g_Q);
    cudaGetSymbolAddress((void**)&KVp, g_KV);
    cudaGetSymbolAddress((void**)&ctxp, g_ctx);
    cudaGetSymbolAddress((void**)&attp, g_att);

    cudaFuncSetAttribute(attn_kernel, cudaFuncAttributeMaxDynamicSharedMemorySize, ATTN_SMEM);

    // Q = text @ Wq^T + bq
    sgemm_bias<<<dim3(DIM / BN, MQ / BM), 256>>>(text, ipw, ipb, nullptr, Qp, MQ, DIM, DIM);
    // [K|V] = vision @ [Wk|Wv]^T + [bk|bv]   (N = 2048)
    sgemm_bias<<<dim3(2 * DIM / BN, MK / BM), 256>>>(vision, ipw + (size_t)DIM * DIM, ipb + DIM,
                                                     nullptr, KVp, MK, 2 * DIM, DIM);
    // fused attention: writes g_ctx and attn_weights (second half of d_out)
    attn_kernel<<<NB * (LQ / 32), 256, ATTN_SMEM>>>(attnw);
    // attended = ctx @ out_w^T + out_b + text  (residual fused)
    sgemm_bias<<<dim3(DIM / BN, MQ / BM), 256>>>(ctxp, outw, outb, text, attp, MQ, DIM, DIM);
    // out = layernorm(attended)
    ln_kernel<<<MQ, 256>>>(attp, lng, lnb, out);
}

// round 3
// speedup vs baseline: 1.3332x; 1.3332x over previous
#include <cuda_runtime.h>
#include <cuda_bf16.h>
#include <cstdint>
#include <cstddef>

#define DIM 1024
#define NH 16
#define HD 64
#define NB 8
#define LQ 512
#define LKK 1024
#define MQ (NB*LQ)      // 4096
#define MK (NB*LKK)     // 8192
#define EPSV 1e-5f
#define QSCALE 0.125f

typedef unsigned long long ull;

// ------------------------- scratch (static device globals) -------------------------
__device__ float g_Q[(size_t)MQ * DIM];
__device__ float g_KV[(size_t)MK * 2 * DIM];
__device__ float g_ctx[(size_t)MQ * DIM];
__device__ float g_att[(size_t)MQ * DIM];

// bf16 hi/lo split buffers
__device__ __nv_bfloat16 g_tAhi[(size_t)MQ * DIM],  g_tAlo[(size_t)MQ * DIM];
__device__ __nv_bfloat16 g_tVhi[(size_t)MK * DIM],  g_tVlo[(size_t)MK * DIM];
__device__ __nv_bfloat16 g_tWhi[(size_t)3*DIM*DIM], g_tWlo[(size_t)3*DIM*DIM];
__device__ __nv_bfloat16 g_tOhi[(size_t)DIM*DIM],   g_tOlo[(size_t)DIM*DIM];
__device__ __nv_bfloat16 g_tChi[(size_t)MQ * DIM],  g_tClo[(size_t)MQ * DIM];

// ------------------------- helpers -------------------------
__device__ __forceinline__ uint32_t smem_to_u32(const void* p) {
    uint32_t a;
    asm("{ .reg .u64 t; cvta.to.shared.u64 t, %1; cvt.u32.u64 %0, t; }" : "=r"(a) : "l"(p));
    return a;
}
__device__ __forceinline__ void ldsm_x4(uint32_t& r0, uint32_t& r1, uint32_t& r2, uint32_t& r3, uint32_t addr) {
    asm volatile("ldmatrix.sync.aligned.m8n8.x4.shared.b16 {%0,%1,%2,%3}, [%4];"
        : "=r"(r0), "=r"(r1), "=r"(r2), "=r"(r3) : "r"(addr));
}
__device__ __forceinline__ void mma16816(float* d, const uint32_t* a, const uint32_t* b) {
    asm volatile("mma.sync.aligned.m16n8k16.row.col.f32.bf16.bf16.f32 "
        "{%0,%1,%2,%3}, {%4,%5,%6,%7}, {%8,%9}, {%0,%1,%2,%3};"
        : "+f"(d[0]), "+f"(d[1]), "+f"(d[2]), "+f"(d[3])
        : "r"(a[0]), "r"(a[1]), "r"(a[2]), "r"(a[3]), "r"(b[0]), "r"(b[1]));
}

// packed f32x2 helpers (attention kernel)
__device__ __forceinline__ ull pack2(float lo, float hi) {
    ull r; asm("mov.b64 %0, {%1, %2};" : "=l"(r) : "f"(lo), "f"(hi)); return r;
}
__device__ __forceinline__ void fma2(ull& d, ull a, ull b) {
    asm("fma.rn.f32x2 %0, %1, %2, %3;" : "=l"(d) : "l"(a), "l"(b), "l"(d));
}
__device__ __forceinline__ float2 unpack2(ull v) {
    float2 r; asm("mov.b64 {%0, %1}, %2;" : "=f"(r.x), "=f"(r.y) : "l"(v)); return r;
}

// ------------------------- fp32 -> (bf16 hi, bf16 lo) split -------------------------
__global__ __launch_bounds__(256) void cvt_pair(const float4* __restrict__ x,
                                                __nv_bfloat162* __restrict__ hi,
                                                __nv_bfloat162* __restrict__ lo, int n4)
{
    int i = blockIdx.x * blockDim.x + threadIdx.x;
    if (i >= n4) return;
    float4 v = x[i];
    __nv_bfloat162 hA = __floats2bfloat162_rn(v.x, v.y);
    __nv_bfloat162 hB = __floats2bfloat162_rn(v.z, v.w);
    __nv_bfloat162 lA = __floats2bfloat162_rn(v.x - __low2float(hA), v.y - __high2float(hA));
    __nv_bfloat162 lB = __floats2bfloat162_rn(v.z - __low2float(hB), v.w - __high2float(hB));
    hi[2 * i] = hA; hi[2 * i + 1] = hB;
    lo[2 * i] = lA; lo[2 * i + 1] = lB;
}

// ------------------------- mma.sync bf16x3 GEMM -------------------------
// C[M,N] = A[M,K] @ W[N,K]^T + bias (+res). A,W as bf16 hi/lo pairs.
// CTA tile 128x128, K chunk 64. Warp grid 2(m) x 4(n), warp tile 64x32.
// smem tiles: 128 rows x 128 bytes, 128B XOR swizzle -> conflict-free ldmatrix.
#define KC 64
#define TILE_B 16384
#define GSM_TOTAL (4 * TILE_B)

__global__ __launch_bounds__(256) void gemm_mma(
    const __nv_bfloat16* __restrict__ Ahi, const __nv_bfloat16* __restrict__ Alo,
    const __nv_bfloat16* __restrict__ Whi, const __nv_bfloat16* __restrict__ Wlo,
    const float* __restrict__ bias, const float* __restrict__ res,
    float* __restrict__ C, int M, int N, int K)
{
    extern __shared__ char sm[];
    char* sAhi = sm;
    char* sAlo = sm + TILE_B;
    char* sWhi = sm + 2 * TILE_B;
    char* sWlo = sm + 3 * TILE_B;

    const int tid  = threadIdx.x;
    const int wid  = tid >> 5;
    const int lane = tid & 31;
    const int bm = blockIdx.y * 128;
    const int bn = blockIdx.x * 128;
    const int m0 = (wid >> 2) * 64;   // warp m offset in tile
    const int n0 = (wid & 3) * 32;    // warp n offset in tile

    // ---- per-thread smem store slots (4 x 16B per tile) ----
    int srow[4], soff[4], scu[4];
#pragma unroll
    for (int i = 0; i < 4; i++) {
        int u = tid + i * 256;
        srow[i] = u >> 3;
        scu[i]  = u & 7;
        soff[i] = srow[i] * 128 + ((scu[i] * 16) ^ ((srow[i] & 7) << 4));
    }

    // ---- ldmatrix addresses ----
    // A frag (m16k16): row = m0 + mf*16 + (lane&15), kbyte = ks*32 + (lane>>4)*16
    const int arow_l = (lane & 15);
    const int axor   = (arow_l & 7) << 4;
    const int akb    = (lane >> 4) * 16;
    uint32_t aAhi = smem_to_u32(sAhi), aAlo = smem_to_u32(sAlo);
    uint32_t aWhi = smem_to_u32(sWhi), aWlo = smem_to_u32(sWlo);
    uint32_t abase[4];
#pragma unroll
    for (int mf = 0; mf < 4; mf++)
        abase[mf] = (uint32_t)((m0 + mf * 16 + arow_l) * 128);

    // B frag pair (two n8 frags): row = n0 + np*16 + (lane&7) + ((lane&16)?8:0),
    // kbyte = ks*32 + ((lane&8)?16:0)
    const int brow_l = (lane & 7) + ((lane & 16) ? 8 : 0);
    const int bxor   = (lane & 7) << 4;
    const int bkb    = (lane & 8) ? 16 : 0;
    uint32_t bbase[2];
#pragma unroll
    for (int np = 0; np < 2; np++)
        bbase[np] = (uint32_t)((n0 + np * 16 + brow_l) * 128);

    float acc[4][4][4];
#pragma unroll
    for (int i = 0; i < 4; i++)
#pragma unroll
        for (int j = 0; j < 4; j++)
#pragma unroll
            for (int l = 0; l < 4; l++) acc[i][j][l] = 0.f;

    const int nchunks = K / KC;
    for (int c = 0; c < nchunks; c++) {
        const size_t coff = (size_t)c * KC;
        __syncthreads();
#pragma unroll
        for (int i = 0; i < 4; i++) {
            size_t arow = (size_t)(bm + srow[i]) * K + coff + scu[i] * 8;
            size_t wrow = (size_t)(bn + srow[i]) * K + coff + scu[i] * 8;
            *(uint4*)(sAhi + soff[i]) = *(const uint4*)(Ahi + arow);
            *(uint4*)(sAlo + soff[i]) = *(const uint4*)(Alo + arow);
            *(uint4*)(sWhi + soff[i]) = *(const uint4*)(Whi + wrow);
            *(uint4*)(sWlo + soff[i]) = *(const uint4*)(Wlo + wrow);
        }
        __syncthreads();
#pragma unroll
        for (int ks = 0; ks < 4; ks++) {
            const int akoff = (ks * 32 + akb) ^ axor;
            const int bkoff = (ks * 32 + bkb) ^ bxor;
            uint32_t ah[4][4], al[4][4];
#pragma unroll
            for (int mf = 0; mf < 4; mf++) {
                ldsm_x4(ah[mf][0], ah[mf][1], ah[mf][2], ah[mf][3], aAhi + abase[mf] + akoff);
                ldsm_x4(al[mf][0], al[mf][1], al[mf][2], al[mf][3], aAlo + abase[mf] + akoff);
            }
            uint32_t bh[2][4], bl[2][4];
#pragma unroll
            for (int np = 0; np < 2; np++) {
                ldsm_x4(bh[np][0], bh[np][1], bh[np][2], bh[np][3], aWhi + bbase[np] + bkoff);
                ldsm_x4(bl[np][0], bl[np][1], bl[np][2], bl[np][3], aWlo + bbase[np] + bkoff);
            }
#pragma unroll
            for (int mf = 0; mf < 4; mf++)
#pragma unroll
                for (int np = 0; np < 2; np++)
#pragma unroll
                    for (int half = 0; half < 2; half++) {
                        float* d = acc[mf][np * 2 + half];
                        mma16816(d, ah[mf], &bh[np][half * 2]);   // hi*hi
                        mma16816(d, ah[mf], &bl[np][half * 2]);   // hi*lo
                        mma16816(d, al[mf], &bh[np][half * 2]);   // lo*hi
                    }
        }
    }

    // ---- epilogue ----
    const int gid = lane >> 2;          // group id 0..7
    const int tig = lane & 3;           // thread in group
#pragma unroll
    for (int mf = 0; mf < 4; mf++) {
        const int mrow0 = bm + m0 + mf * 16 + gid;
#pragma unroll
        for (int nf = 0; nf < 4; nf++) {
            const int col = bn + n0 + nf * 8 + tig * 2;
            const float2 bia = *(const float2*)&bias[col];
            float* d = acc[mf][nf];
            float2 o0 = make_float2(d[0] + bia.x, d[1] + bia.y);
            float2 o1 = make_float2(d[2] + bia.x, d[3] + bia.y);
            const size_t i0 = (size_t)mrow0 * N + col;
            const size_t i1 = (size_t)(mrow0 + 8) * N + col;
            if (res) {
                float2 r0 = *(const float2*)&res[i0];
                float2 r1 = *(const float2*)&res[i1];
                o0.x += r0.x; o0.y += r0.y;
                o1.x += r1.x; o1.y += r1.y;
            }
            *(float2*)&C[i0] = o0;
            *(float2*)&C[i1] = o1;
        }
    }
}

// ------------------------- fused attention (f32x2, as in R1) -------------------------
#define ATTN_SMEM ((32*LKK + 32*HD + HD*68 + 64*HD) * 4)

__global__ __launch_bounds__(256) void attn_kernel(float* __restrict__ attnw)
{
    extern __shared__ float smf[];
    float* S  = smf;
    float* Qs = smf + 32 * LKK;
    float* KT = Qs + 32 * HD;
    float* Vs = KT + HD * 68;

    const int tid = threadIdx.x;
    const int b  = blockIdx.x >> 4;
    const int q0 = (blockIdx.x & 15) << 5;
    const int tq = tid >> 4;
    const int tk = tid & 15;

    for (int h = 0; h < NH; h++) {
#pragma unroll
        for (int i = 0; i < 2; i++) {
            int f = tid + i * 256;
            int q = f >> 4;
            int d4 = (f & 15) << 2;
            float4 v = *(const float4*)&g_Q[((size_t)(b * LQ + q0 + q)) * DIM + h * HD + d4];
            v.x *= QSCALE; v.y *= QSCALE; v.z *= QSCALE; v.w *= QSCALE;
            *(float4*)&Qs[q * HD + d4] = v;
        }
        for (int kc = 0; kc < LKK / 64; kc++) {
            __syncthreads();
#pragma unroll
            for (int i = 0; i < 4; i++) {
                int f = tid + i * 256;
                int kk = f >> 4;
                int d4 = (f & 15) << 2;
                float4 v = *(const float4*)&g_KV[((size_t)(b * LKK + kc * 64 + kk)) * (2 * DIM) + h * HD + d4];
                KT[(d4 + 0) * 68 + kk] = v.x;
                KT[(d4 + 1) * 68 + kk] = v.y;
                KT[(d4 + 2) * 68 + kk] = v.z;
                KT[(d4 + 3) * 68 + kk] = v.w;
            }
            __syncthreads();
            ull a00 = 0, a01 = 0, a10 = 0, a11 = 0;
            const float* qp0 = &Qs[(2 * tq) * HD];
            const float* qp1 = &Qs[(2 * tq + 1) * HD];
#pragma unroll 8
            for (int d = 0; d < HD; d++) {
                float qa = qp0[d], qb = qp1[d];
                float4 kv = *(const float4*)&KT[d * 68 + 4 * tk];
                ull qa2 = pack2(qa, qa), qb2 = pack2(qb, qb);
                ull k01 = pack2(kv.x, kv.y), k23 = pack2(kv.z, kv.w);
                fma2(a00, qa2, k01); fma2(a01, qa2, k23);
                fma2(a10, qb2, k01); fma2(a11, qb2, k23);
            }
            float2 r0 = unpack2(a00), r1 = unpack2(a01);
            *(float4*)&S[(2 * tq) * LKK + kc * 64 + 4 * tk] = make_float4(r0.x, r0.y, r1.x, r1.y);
            r0 = unpack2(a10); r1 = unpack2(a11);
            *(float4*)&S[(2 * tq + 1) * LKK + kc * 64 + 4 * tk] = make_float4(r0.x, r0.y, r1.x, r1.y);
        }
        __syncthreads();
        {
            const int w = tid >> 5, lane = tid & 31;
            for (int r = w * 4; r < w * 4 + 4; r++) {
                float* row = &S[r * LKK];
                float mx = -1e30f;
#pragma unroll
                for (int j = 0; j < LKK / 32; j++) mx = fmaxf(mx, row[j * 32 + lane]);
#pragma unroll
                for (int o = 16; o > 0; o >>= 1) mx = fmaxf(mx, __shfl_xor_sync(0xffffffffu, mx, o));
                float s = 0.f;
#pragma unroll
                for (int j = 0; j < LKK / 32; j++) {
                    float e = __expf(row[j * 32 + lane] - mx);
                    row[j * 32 + lane] = e;
                    s += e;
                }
#pragma unroll
                for (int o = 16; o > 0; o >>= 1) s += __shfl_xor_sync(0xffffffffu, s, o);
                float inv = 1.0f / s;
#pragma unroll
                for (int j = 0; j < LKK / 32; j++) row[j * 32 + lane] *= inv;
            }
        }
        __syncthreads();
        {
            float4* aw4 = (float4*)(attnw + ((size_t)(b * LQ + q0)) * LKK);
            const float4* S4 = (const float4*)S;
            const float invh = 1.0f / NH;
            if (h == 0) {
                for (int f = tid; f < 32 * LKK / 4; f += 256) {
                    float4 p = S4[f];
                    p.x *= invh; p.y *= invh; p.z *= invh; p.w *= invh;
                    aw4[f] = p;
                }
            } else {
                for (int f = tid; f < 32 * LKK / 4; f += 256) {
                    float4 p = S4[f];
                    float4 o = aw4[f];
                    o.x += p.x * invh; o.y += p.y * invh; o.z += p.z * invh; o.w += p.w * invh;
                    aw4[f] = o;
                }
            }
        }
        ull c00 = 0, c01 = 0, c10 = 0, c11 = 0;
        for (int kc = 0; kc < LKK / 64; kc++) {
            __syncthreads();
#pragma unroll
            for (int i = 0; i < 4; i++) {
                int f = tid + i * 256;
                int kk = f >> 4;
                int d4 = (f & 15) << 2;
                float4 v = *(const float4*)&g_KV[((size_t)(b * LKK + kc * 64 + kk)) * (2 * DIM) + DIM + h * HD + d4];
                *(float4*)&Vs[kk * HD + d4] = v;
            }
            __syncthreads();
            const float* p0 = &S[(2 * tq) * LKK + kc * 64];
            const float* p1 = &S[(2 * tq + 1) * LKK + kc * 64];
#pragma unroll 8
            for (int kk = 0; kk < 64; kk++) {
                float pa = p0[kk], pb = p1[kk];
                float4 vv = *(const float4*)&Vs[kk * HD + 4 * tk];
                ull pa2 = pack2(pa, pa), pb2 = pack2(pb, pb);
                ull v01 = pack2(vv.x, vv.y), v23 = pack2(vv.z, vv.w);
                fma2(c00, pa2, v01); fma2(c01, pa2, v23);
                fma2(c10, pb2, v01); fma2(c11, pb2, v23);
            }
        }
        {
            float2 r0 = unpack2(c00), r1 = unpack2(c01);
            *(float4*)&g_ctx[((size_t)(b * LQ + q0 + 2 * tq)) * DIM + h * HD + 4 * tk] =
                make_float4(r0.x, r0.y, r1.x, r1.y);
            r0 = unpack2(c10); r1 = unpack2(c11);
            *(float4*)&g_ctx[((size_t)(b * LQ + q0 + 2 * tq + 1)) * DIM + h * HD + 4 * tk] =
                make_float4(r0.x, r0.y, r1.x, r1.y);
        }
    }
}

// ------------------------- layernorm -------------------------
__global__ __launch_bounds__(256) void ln_kernel(
    const float* __restrict__ X, const float* __restrict__ gam,
    const float* __restrict__ bet, float* __restrict__ out)
{
    __shared__ float red[64];
    __shared__ float s_mu, s_rinv;
    const int r = blockIdx.x, tid = threadIdx.x;
    const float* x = X + (size_t)r * DIM;
    float4 v = *(const float4*)&x[tid * 4];
    float s  = v.x + v.y + v.z + v.w;
    float sq = v.x * v.x + v.y * v.y + v.z * v.z + v.w * v.w;
#pragma unroll
    for (int o = 16; o > 0; o >>= 1) {
        s  += __shfl_xor_sync(0xffffffffu, s, o);
        sq += __shfl_xor_sync(0xffffffffu, sq, o);
    }
    const int w = tid >> 5;
    if ((tid & 31) == 0) { red[w] = s; red[32 + w] = sq; }
    __syncthreads();
    if (tid == 0) {
        float S = 0, Q = 0;
        for (int i = 0; i < 8; i++) { S += red[i]; Q += red[32 + i]; }
        float mu = S * (1.0f / DIM);
        float var = Q * (1.0f / DIM) - mu * mu;
        s_mu = mu;
        s_rinv = rsqrtf(var + EPSV);
    }
    __syncthreads();
    const float mu = s_mu, rinv = s_rinv;
    float4 gg = *(const float4*)&gam[tid * 4];
    float4 bb = *(const float4*)&bet[tid * 4];
    float4 o;
    o.x = (v.x - mu) * rinv * gg.x + bb.x;
    o.y = (v.y - mu) * rinv * gg.y + bb.y;
    o.z = (v.z - mu) * rinv * gg.z + bb.z;
    o.w = (v.w - mu) * rinv * gg.w + bb.w;
    *(float4*)&out[(size_t)r * DIM + tid * 4] = o;
}

// ------------------------- launch -------------------------
extern "C" void kernel_launch(void* const* d_in, const int* in_sizes, int n_in,
                              void* d_out, int out_size)
{
    const float* text   = (const float*)d_in[0];
    const float* vision = (const float*)d_in[1];
    const float* ipw    = (const float*)d_in[2];
    const float* ipb    = (const float*)d_in[3];
    const float* outw   = (const float*)d_in[4];
    const float* outb   = (const float*)d_in[5];
    const float* lng    = (const float*)d_in[6];
    const float* lnb    = (const float*)d_in[7];

    float* out   = (float*)d_out;
    float* attnw = out + (size_t)MQ * DIM;

    float *Qp, *KVp, *ctxp, *attp;
    cudaGetSymbolAddress((void**)&Qp, g_Q);
    cudaGetSymbolAddress((void**)&KVp, g_KV);
    cudaGetSymbolAddress((void**)&ctxp, g_ctx);
    cudaGetSymbolAddress((void**)&attp, g_att);

    __nv_bfloat16 *tAhi, *tAlo, *tVhi, *tVlo, *tWhi, *tWlo, *tOhi, *tOlo, *tChi, *tClo;
    cudaGetSymbolAddress((void**)&tAhi, g_tAhi); cudaGetSymbolAddress((void**)&tAlo, g_tAlo);
    cudaGetSymbolAddress((void**)&tVhi, g_tVhi); cudaGetSymbolAddress((void**)&tVlo, g_tVlo);
    cudaGetSymbolAddress((void**)&tWhi, g_tWhi); cudaGetSymbolAddress((void**)&tWlo, g_tWlo);
    cudaGetSymbolAddress((void**)&tOhi, g_tOhi); cudaGetSymbolAddress((void**)&tOlo, g_tOlo);
    cudaGetSymbolAddress((void**)&tChi, g_tChi); cudaGetSymbolAddress((void**)&tClo, g_tClo);

    cudaFuncSetAttribute(attn_kernel, cudaFuncAttributeMaxDynamicSharedMemorySize, ATTN_SMEM);
    cudaFuncSetAttribute(gemm_mma, cudaFuncAttributeMaxDynamicSharedMemorySize, GSM_TOTAL);

    // fp32 -> bf16 hi/lo splits
    {
        int n4;
        n4 = (MQ * DIM) / 4;
        cvt_pair<<<(n4 + 255) / 256, 256>>>((const float4*)text, (__nv_bfloat162*)tAhi, (__nv_bfloat162*)tAlo, n4);
        n4 = (MK * DIM) / 4;
        cvt_pair<<<(n4 + 255) / 256, 256>>>((const float4*)vision, (__nv_bfloat162*)tVhi, (__nv_bfloat162*)tVlo, n4);
        n4 = (3 * DIM * DIM) / 4;
        cvt_pair<<<(n4 + 255) / 256, 256>>>((const float4*)ipw, (__nv_bfloat162*)tWhi, (__nv_bfloat162*)tWlo, n4);
        n4 = (DIM * DIM) / 4;
        cvt_pair<<<(n4 + 255) / 256, 256>>>((const float4*)outw, (__nv_bfloat162*)tOhi, (__nv_bfloat162*)tOlo, n4);
    }

    // Q = text @ Wq^T + bq
    gemm_mma<<<dim3(DIM / 128, MQ / 128), 256, GSM_TOTAL>>>(
        tAhi, tAlo, tWhi, tWlo, ipb, nullptr, Qp, MQ, DIM, DIM);
    // [K|V] = vision @ [Wk|Wv]^T + [bk|bv]
    gemm_mma<<<dim3(2 * DIM / 128, MK / 128), 256, GSM_TOTAL>>>(
        tVhi, tVlo, tWhi + (size_t)DIM * DIM, tWlo + (size_t)DIM * DIM,
        ipb + DIM, nullptr, KVp, MK, 2 * DIM, DIM);
    // attention
    attn_kernel<<<NB * (LQ / 32), 256, ATTN_SMEM>>>(attnw);
    // ctx -> bf16 split
    {
        int n4 = (MQ * DIM) / 4;
        cvt_pair<<<(n4 + 255) / 256, 256>>>((const float4*)ctxp, (__nv_bfloat162*)tChi, (__nv_bfloat162*)tClo, n4);
    }
    // attended = ctx @ out_w^T + out_b + text
    gemm_mma<<<dim3(DIM / 128, MQ / 128), 256, GSM_TOTAL>>>(
        tChi, tClo, tOhi, tOlo, outb, text, attp, MQ, DIM, DIM);
    // layernorm
    ln_kernel<<<MQ, 256>>>(attp, lng, lnb, out);
}

// round 4
// speedup vs baseline: 2.0348x; 1.5262x over previous
#include <cuda_runtime.h>
#include <cuda_bf16.h>
#include <cstdint>
#include <cstddef>

#define DIM 1024
#define NH 16
#define HD 64
#define NB 8
#define LQ 512
#define LKK 1024
#define MQ (NB*LQ)      // 4096
#define MK (NB*LKK)     // 8192
#define EPSV 1e-5f
#define QSCALE 0.125f

// ------------------------- scratch -------------------------
__device__ float g_att[(size_t)MQ * DIM];

// hi/lo bf16 split buffers
__device__ __nv_bfloat16 g_tAhi[(size_t)MQ * DIM],  g_tAlo[(size_t)MQ * DIM];     // text
__device__ __nv_bfloat16 g_tVhi[(size_t)MK * DIM],  g_tVlo[(size_t)MK * DIM];     // vision
__device__ __nv_bfloat16 g_tWhi[(size_t)3*DIM*DIM], g_tWlo[(size_t)3*DIM*DIM];    // in_proj_w
__device__ __nv_bfloat16 g_tOhi[(size_t)DIM*DIM],   g_tOlo[(size_t)DIM*DIM];      // out_w
__device__ __nv_bfloat16 g_Qhi[(size_t)MQ * DIM],   g_Qlo[(size_t)MQ * DIM];      // scaled Q
__device__ __nv_bfloat16 g_Khi[(size_t)MK * DIM],   g_Klo[(size_t)MK * DIM];
__device__ __nv_bfloat16 g_Vhi[(size_t)MK * DIM],   g_Vlo[(size_t)MK * DIM];
__device__ __nv_bfloat16 g_Chi[(size_t)MQ * DIM],   g_Clo[(size_t)MQ * DIM];      // ctx

// ------------------------- helpers -------------------------
__device__ __forceinline__ uint32_t smem_to_u32(const void* p) {
    uint32_t a;
    asm("{ .reg .u64 t; cvta.to.shared.u64 t, %1; cvt.u32.u64 %0, t; }" : "=r"(a) : "l"(p));
    return a;
}
__device__ __forceinline__ void ldsm_x4(uint32_t* r, uint32_t addr) {
    asm volatile("ldmatrix.sync.aligned.m8n8.x4.shared.b16 {%0,%1,%2,%3}, [%4];"
        : "=r"(r[0]), "=r"(r[1]), "=r"(r[2]), "=r"(r[3]) : "r"(addr));
}
__device__ __forceinline__ void ldsm_x4_t(uint32_t* r, uint32_t addr) {
    asm volatile("ldmatrix.sync.aligned.m8n8.x4.trans.shared.b16 {%0,%1,%2,%3}, [%4];"
        : "=r"(r[0]), "=r"(r[1]), "=r"(r[2]), "=r"(r[3]) : "r"(addr));
}
__device__ __forceinline__ void mma16816(float* d, const uint32_t* a, const uint32_t* b) {
    asm volatile("mma.sync.aligned.m16n8k16.row.col.f32.bf16.bf16.f32 "
        "{%0,%1,%2,%3}, {%4,%5,%6,%7}, {%8,%9}, {%0,%1,%2,%3};"
        : "+f"(d[0]), "+f"(d[1]), "+f"(d[2]), "+f"(d[3])
        : "r"(a[0]), "r"(a[1]), "r"(a[2]), "r"(a[3]), "r"(b[0]), "r"(b[1]));
}
__device__ __forceinline__ void split2(float a, float b, uint32_t& hi, uint32_t& lo) {
    __nv_bfloat162 h = __floats2bfloat162_rn(a, b);
    __nv_bfloat162 l = __floats2bfloat162_rn(a - __low2float(h), b - __high2float(h));
    hi = *(uint32_t*)&h; lo = *(uint32_t*)&l;
}

// ------------------------- fp32 -> (bf16 hi, bf16 lo) split -------------------------
__global__ __launch_bounds__(256) void cvt_pair(const float4* __restrict__ x,
                                                __nv_bfloat162* __restrict__ hi,
                                                __nv_bfloat162* __restrict__ lo, int n4)
{
    int i = blockIdx.x * blockDim.x + threadIdx.x;
    if (i >= n4) return;
    float4 v = x[i];
    __nv_bfloat162 hA = __floats2bfloat162_rn(v.x, v.y);
    __nv_bfloat162 hB = __floats2bfloat162_rn(v.z, v.w);
    __nv_bfloat162 lA = __floats2bfloat162_rn(v.x - __low2float(hA), v.y - __high2float(hA));
    __nv_bfloat162 lB = __floats2bfloat162_rn(v.z - __low2float(hB), v.w - __high2float(hB));
    hi[2 * i] = hA; hi[2 * i + 1] = hB;
    lo[2 * i] = lA; lo[2 * i + 1] = lB;
}

// ------------------------- mma.sync bf16x3 GEMM -------------------------
// MODE 0: C = fp32 (acc+bias+res)
// MODE 1: hi0/lo0 = split(QSCALE*(acc+bias))        (N == DIM)
// MODE 2: col<1024 -> hi0/lo0 (K), col>=1024 -> hi1/lo1 (V), width DIM
#define KC 64
#define TILE_B 16384
#define GSM_TOTAL (4 * TILE_B)

template<int MODE>
__global__ __launch_bounds__(256) void gemm_mma(
    const __nv_bfloat16* __restrict__ Ahi, const __nv_bfloat16* __restrict__ Alo,
    const __nv_bfloat16* __restrict__ Whi, const __nv_bfloat16* __restrict__ Wlo,
    const float* __restrict__ bias, const float* __restrict__ res,
    float* __restrict__ C,
    __nv_bfloat16* __restrict__ h0, __nv_bfloat16* __restrict__ l0,
    __nv_bfloat16* __restrict__ h1, __nv_bfloat16* __restrict__ l1,
    int M, int N, int K)
{
    extern __shared__ char sm[];
    char* sAhi = sm;
    char* sAlo = sm + TILE_B;
    char* sWhi = sm + 2 * TILE_B;
    char* sWlo = sm + 3 * TILE_B;

    const int tid  = threadIdx.x;
    const int wid  = tid >> 5;
    const int lane = tid & 31;
    const int bm = blockIdx.y * 128;
    const int bn = blockIdx.x * 128;
    const int m0 = (wid >> 2) * 64;
    const int n0 = (wid & 3) * 32;

    int srow[4], soff[4], scu[4];
#pragma unroll
    for (int i = 0; i < 4; i++) {
        int u = tid + i * 256;
        srow[i] = u >> 3;
        scu[i]  = u & 7;
        soff[i] = srow[i] * 128 + ((scu[i] * 16) ^ ((srow[i] & 7) << 4));
    }

    const int arow_l = (lane & 15);
    const int axor   = (arow_l & 7) << 4;
    const int akb    = (lane >> 4) * 16;
    uint32_t aAhi = smem_to_u32(sAhi), aAlo = smem_to_u32(sAlo);
    uint32_t aWhi = smem_to_u32(sWhi), aWlo = smem_to_u32(sWlo);
    uint32_t abase[4];
#pragma unroll
    for (int mf = 0; mf < 4; mf++)
        abase[mf] = (uint32_t)((m0 + mf * 16 + arow_l) * 128);

    const int brow_l = (lane & 7) + ((lane & 16) ? 8 : 0);
    const int bxor   = (lane & 7) << 4;
    const int bkb    = (lane & 8) ? 16 : 0;
    uint32_t bbase[2];
#pragma unroll
    for (int np = 0; np < 2; np++)
        bbase[np] = (uint32_t)((n0 + np * 16 + brow_l) * 128);

    float acc[4][4][4];
#pragma unroll
    for (int i = 0; i < 4; i++)
#pragma unroll
        for (int j = 0; j < 4; j++)
#pragma unroll
            for (int l = 0; l < 4; l++) acc[i][j][l] = 0.f;

    const int nchunks = K / KC;
    for (int c = 0; c < nchunks; c++) {
        const size_t coff = (size_t)c * KC;
        __syncthreads();
#pragma unroll
        for (int i = 0; i < 4; i++) {
            size_t arow = (size_t)(bm + srow[i]) * K + coff + scu[i] * 8;
            size_t wrow = (size_t)(bn + srow[i]) * K + coff + scu[i] * 8;
            *(uint4*)(sAhi + soff[i]) = *(const uint4*)(Ahi + arow);
            *(uint4*)(sAlo + soff[i]) = *(const uint4*)(Alo + arow);
            *(uint4*)(sWhi + soff[i]) = *(const uint4*)(Whi + wrow);
            *(uint4*)(sWlo + soff[i]) = *(const uint4*)(Wlo + wrow);
        }
        __syncthreads();
#pragma unroll
        for (int ks = 0; ks < 4; ks++) {
            const int akoff = (ks * 32 + akb) ^ axor;
            const int bkoff = (ks * 32 + bkb) ^ bxor;
            uint32_t ah[4][4], al[4][4];
#pragma unroll
            for (int mf = 0; mf < 4; mf++) {
                ldsm_x4(ah[mf], aAhi + abase[mf] + akoff);
                ldsm_x4(al[mf], aAlo + abase[mf] + akoff);
            }
            uint32_t bh[2][4], bl[2][4];
#pragma unroll
            for (int np = 0; np < 2; np++) {
                ldsm_x4(bh[np], aWhi + bbase[np] + bkoff);
                ldsm_x4(bl[np], aWlo + bbase[np] + bkoff);
            }
#pragma unroll
            for (int mf = 0; mf < 4; mf++)
#pragma unroll
                for (int np = 0; np < 2; np++)
#pragma unroll
                    for (int half = 0; half < 2; half++) {
                        float* d = acc[mf][np * 2 + half];
                        mma16816(d, ah[mf], &bh[np][half * 2]);
                        mma16816(d, ah[mf], &bl[np][half * 2]);
                        mma16816(d, al[mf], &bh[np][half * 2]);
                    }
        }
    }

    const int gid = lane >> 2;
    const int tig = lane & 3;
#pragma unroll
    for (int mf = 0; mf < 4; mf++) {
        const int mrow0 = bm + m0 + mf * 16 + gid;
#pragma unroll
        for (int nf = 0; nf < 4; nf++) {
            const int col = bn + n0 + nf * 8 + tig * 2;
            const float2 bia = *(const float2*)&bias[col];
            float* d = acc[mf][nf];
            float v00 = d[0] + bia.x, v01 = d[1] + bia.y;
            float v10 = d[2] + bia.x, v11 = d[3] + bia.y;
            if (MODE == 0) {
                const size_t i0 = (size_t)mrow0 * N + col;
                const size_t i1 = (size_t)(mrow0 + 8) * N + col;
                if (res) {
                    float2 r0 = *(const float2*)&res[i0];
                    float2 r1 = *(const float2*)&res[i1];
                    v00 += r0.x; v01 += r0.y; v10 += r1.x; v11 += r1.y;
                }
                *(float2*)&C[i0] = make_float2(v00, v01);
                *(float2*)&C[i1] = make_float2(v10, v11);
            } else {
                if (MODE == 1) { v00 *= QSCALE; v01 *= QSCALE; v10 *= QSCALE; v11 *= QSCALE; }
                __nv_bfloat16 *H = h0, *L = l0;
                int cc = col;
                if (MODE == 2 && col >= DIM) { H = h1; L = l1; cc = col - DIM; }
                const size_t i0 = (size_t)mrow0 * DIM + cc;
                const size_t i1 = (size_t)(mrow0 + 8) * DIM + cc;
                uint32_t hh, ll;
                split2(v00, v01, hh, ll);
                *(uint32_t*)&H[i0] = hh; *(uint32_t*)&L[i0] = ll;
                split2(v10, v11, hh, ll);
                *(uint32_t*)&H[i1] = hh; *(uint32_t*)&L[i1] = ll;
            }
        }
    }
}

// ------------------------- tensor-core attention -------------------------
// block = (batch, 32-query tile); loops 16 heads.
// smem: S 32x1024 f32 (reused in place as Phi/Plo bf16), Q hi/lo 32x64, K/V chunk 128x64 hi/lo
#define SM_S  0
#define SM_QH 131072
#define SM_QL 135168
#define SM_KH 139264
#define SM_KL 155648
#define ATTN_SMEM 172032

__global__ __launch_bounds__(256) void attn_mma(float* __restrict__ attnw)
{
    extern __shared__ char sm[];
    float* S = (float*)sm;
    const uint32_t sb = smem_to_u32(sm);

    const int tid  = threadIdx.x;
    const int wid  = tid >> 5;
    const int lane = tid & 31;
    const int b  = blockIdx.x >> 4;
    const int q0 = (blockIdx.x & 15) << 5;

    const int ms  = (wid >> 2) * 16;   // warp m offset (score & ctx)
    const int ns  = (wid & 3) * 32;    // warp n offset within 128-key chunk (score)
    const int nv0 = (wid & 3) * 16;    // warp n offset within 64 dims (ctx)

    const int arow_l = lane & 15;
    const int axor   = (arow_l & 7) << 4;
    const int akb    = (lane >> 4) * 16;
    const int brow_l = (lane & 7) + ((lane & 16) ? 8 : 0);
    const int bxor   = (lane & 7) << 4;
    const int bkb    = (lane & 8) ? 16 : 0;
    const int gid = lane >> 2, tig = lane & 3;

    // K/V chunk loader slots
    int krow[4], koff_s[4], kcu[4];
#pragma unroll
    for (int i = 0; i < 4; i++) {
        int u = tid + i * 256;
        krow[i] = u >> 3;
        kcu[i]  = u & 7;
        koff_s[i] = krow[i] * 128 + ((kcu[i] * 16) ^ ((krow[i] & 7) << 4));
    }
    // Q loader slot
    const int qrow = tid >> 3, qcu = tid & 7;
    const int qoff = qrow * 128 + ((qcu * 16) ^ ((qrow & 7) << 4));

    // V trans-load lane address (within chunk, per ks added later)
    const int vkey_l = ((lane >> 3) & 1) * 8 + (lane & 7);
    const int vdim   = nv0 + ((lane >> 4) ? 8 : 0);

    for (int h = 0; h < NH; h++) {
        // ---- load Q hi/lo tile ----
        {
            size_t g = ((size_t)(b * LQ + q0 + qrow)) * DIM + h * HD + qcu * 8;
            *(uint4*)(sm + SM_QH + qoff) = *(const uint4*)(g_Qhi + g);
            *(uint4*)(sm + SM_QL + qoff) = *(const uint4*)(g_Qlo + g);
        }
        __syncthreads();
        uint32_t qh[4][4], ql[4][4];
#pragma unroll
        for (int ks = 0; ks < 4; ks++) {
            int koff = (ks * 32 + akb) ^ axor;
            ldsm_x4(qh[ks], sb + SM_QH + (ms + arow_l) * 128 + koff);
            ldsm_x4(ql[ks], sb + SM_QL + (ms + arow_l) * 128 + koff);
        }

        // ---- scores ----
        for (int kc = 0; kc < 8; kc++) {
            __syncthreads();
#pragma unroll
            for (int i = 0; i < 4; i++) {
                size_t g = ((size_t)(b * LKK + kc * 128 + krow[i])) * DIM + h * HD + kcu[i] * 8;
                *(uint4*)(sm + SM_KH + koff_s[i]) = *(const uint4*)(g_Khi + g);
                *(uint4*)(sm + SM_KL + koff_s[i]) = *(const uint4*)(g_Klo + g);
            }
            __syncthreads();
            float acc[4][4];
#pragma unroll
            for (int i = 0; i < 4; i++)
#pragma unroll
                for (int j = 0; j < 4; j++) acc[i][j] = 0.f;
#pragma unroll
            for (int ks = 0; ks < 4; ks++) {
                const int bkoff = (ks * 32 + bkb) ^ bxor;
                uint32_t bh[2][4], bl[2][4];
#pragma unroll
                for (int np = 0; np < 2; np++) {
                    ldsm_x4(bh[np], sb + SM_KH + (ns + np * 16 + brow_l) * 128 + bkoff);
                    ldsm_x4(bl[np], sb + SM_KL + (ns + np * 16 + brow_l) * 128 + bkoff);
                }
#pragma unroll
                for (int np = 0; np < 2; np++)
#pragma unroll
                    for (int half = 0; half < 2; half++) {
                        float* d = acc[np * 2 + half];
                        mma16816(d, qh[ks], &bh[np][half * 2]);
                        mma16816(d, qh[ks], &bl[np][half * 2]);
                        mma16816(d, ql[ks], &bh[np][half * 2]);
                    }
            }
#pragma unroll
            for (int nf = 0; nf < 4; nf++) {
                const int col = kc * 128 + ns + nf * 8 + tig * 2;
                *(float2*)&S[(ms + gid) * LKK + col]     = make_float2(acc[nf][0], acc[nf][1]);
                *(float2*)&S[(ms + gid + 8) * LKK + col] = make_float2(acc[nf][2], acc[nf][3]);
            }
        }
        __syncthreads();

        // ---- softmax (8 warps x 4 rows) ----
        {
            for (int r = wid * 4; r < wid * 4 + 4; r++) {
                float* row = &S[r * LKK];
                float mx = -1e30f;
#pragma unroll
                for (int j = 0; j < LKK / 32; j++) mx = fmaxf(mx, row[j * 32 + lane]);
#pragma unroll
                for (int o = 16; o > 0; o >>= 1) mx = fmaxf(mx, __shfl_xor_sync(0xffffffffu, mx, o));
                float s = 0.f;
#pragma unroll
                for (int j = 0; j < LKK / 32; j++) {
                    float e = __expf(row[j * 32 + lane] - mx);
                    row[j * 32 + lane] = e;
                    s += e;
                }
#pragma unroll
                for (int o = 16; o > 0; o >>= 1) s += __shfl_xor_sync(0xffffffffu, s, o);
                float inv = 1.0f / s;
#pragma unroll
                for (int j = 0; j < LKK / 32; j++) row[j * 32 + lane] *= inv;
            }
        }
        __syncthreads();

        // ---- attn_weights accumulation (mean over heads) ----
        {
            float4* aw4 = (float4*)(attnw + ((size_t)(b * LQ + q0)) * LKK);
            const float4* S4 = (const float4*)S;
            const float invh = 1.0f / NH;
            if (h == 0) {
                for (int f = tid; f < 32 * LKK / 4; f += 256) {
                    float4 p = S4[f];
                    p.x *= invh; p.y *= invh; p.z *= invh; p.w *= invh;
                    aw4[f] = p;
                }
            } else {
                for (int f = tid; f < 32 * LKK / 4; f += 256) {
                    float4 p = S4[f];
                    float4 o = aw4[f];
                    o.x += p.x * invh; o.y += p.y * invh; o.z += p.z * invh; o.w += p.w * invh;
                    aw4[f] = o;
                }
            }
        }
        __syncthreads();

        // ---- convert S rows to Phi/Plo bf16 in place ----
        // row r (4KB): Phi bytes [0,2048), Plo [2048,4096), both XOR-swizzled by ((r&7)<<4)
        for (int r = wid * 4; r < wid * 4 + 4; r++) {
            float v[32];
            const float* row = &S[r * LKK + lane * 32];
#pragma unroll
            for (int j = 0; j < 8; j++) *(float4*)&v[j * 4] = *(const float4*)&row[j * 4];
            __syncwarp();
            char* rb = sm + r * 4096;
            const int sw = (r & 7) << 4;
#pragma unroll
            for (int j = 0; j < 4; j++) {
                uint32_t h4[4], l4[4];
#pragma unroll
                for (int p = 0; p < 4; p++)
                    split2(v[j * 8 + p * 2], v[j * 8 + p * 2 + 1], h4[p], l4[p]);
                const int off = ((lane * 4 + j) * 16) ^ sw;
                *(uint4*)(rb + off)        = *(uint4*)h4;
                *(uint4*)(rb + 2048 + off) = *(uint4*)l4;
            }
            __syncwarp();
        }
        __syncthreads();

        // ---- ctx = P @ V ----
        float cacc[2][4];
#pragma unroll
        for (int g = 0; g < 2; g++)
#pragma unroll
            for (int l = 0; l < 4; l++) cacc[g][l] = 0.f;

        for (int kc = 0; kc < 8; kc++) {
            __syncthreads();
#pragma unroll
            for (int i = 0; i < 4; i++) {
                size_t g = ((size_t)(b * LKK + kc * 128 + krow[i])) * DIM + h * HD + kcu[i] * 8;
                *(uint4*)(sm + SM_KH + koff_s[i]) = *(const uint4*)(g_Vhi + g);
                *(uint4*)(sm + SM_KL + koff_s[i]) = *(const uint4*)(g_Vlo + g);
            }
            __syncthreads();
            const int mrow = ms + arow_l;
            const uint32_t pbase = sb + mrow * 4096;
            const int psw = (mrow & 7) << 4;
#pragma unroll
            for (int ks = 0; ks < 8; ks++) {
                const int pk = ((kc * 0) + ks) * 32 + akb;   // kbyte within row's 2KB: local to chunk
                const int poff = ((kc * 256 + pk) ^ psw);
                uint32_t pah[4], pal[4];
                ldsm_x4(pah, pbase + poff);
                ldsm_x4(pal, pbase + 2048 + poff);
                const int key = ks * 16 + vkey_l;
                const uint32_t vaddr = key * 128 + ((vdim * 2) ^ ((key & 7) << 4));
                uint32_t vh[4], vl[4];
                ldsm_x4_t(vh, sb + SM_KH + vaddr);
                ldsm_x4_t(vl, sb + SM_KL + vaddr);
#pragma unroll
                for (int g = 0; g < 2; g++) {
                    float* d = cacc[g];
                    mma16816(d, pah, &vh[g * 2]);
                    mma16816(d, pah, &vl[g * 2]);
                    mma16816(d, pal, &vh[g * 2]);
                }
            }
        }
        // ---- write ctx as bf16 hi/lo ----
#pragma unroll
        for (int g = 0; g < 2; g++) {
            const int col = h * HD + nv0 + g * 8 + tig * 2;
            const size_t i0 = ((size_t)(b * LQ + q0 + ms + gid)) * DIM + col;
            const size_t i1 = ((size_t)(b * LQ + q0 + ms + gid + 8)) * DIM + col;
            uint32_t hh, ll;
            split2(cacc[g][0], cacc[g][1], hh, ll);
            *(uint32_t*)&g_Chi[i0] = hh; *(uint32_t*)&g_Clo[i0] = ll;
            split2(cacc[g][2], cacc[g][3], hh, ll);
            *(uint32_t*)&g_Chi[i1] = hh; *(uint32_t*)&g_Clo[i1] = ll;
        }
        __syncthreads();
    }
}

// ------------------------- layernorm -------------------------
__global__ __launch_bounds__(256) void ln_kernel(
    const float* __restrict__ X, const float* __restrict__ gam,
    const float* __restrict__ bet, float* __restrict__ out)
{
    __shared__ float red[64];
    __shared__ float s_mu, s_rinv;
    const int r = blockIdx.x, tid = threadIdx.x;
    const float* x = X + (size_t)r * DIM;
    float4 v = *(const float4*)&x[tid * 4];
    float s  = v.x + v.y + v.z + v.w;
    float sq = v.x * v.x + v.y * v.y + v.z * v.z + v.w * v.w;
#pragma unroll
    for (int o = 16; o > 0; o >>= 1) {
        s  += __shfl_xor_sync(0xffffffffu, s, o);
        sq += __shfl_xor_sync(0xffffffffu, sq, o);
    }
    const int w = tid >> 5;
    if ((tid & 31) == 0) { red[w] = s; red[32 + w] = sq; }
    __syncthreads();
    if (tid == 0) {
        float S = 0, Q = 0;
        for (int i = 0; i < 8; i++) { S += red[i]; Q += red[32 + i]; }
        float mu = S * (1.0f / DIM);
        float var = Q * (1.0f / DIM) - mu * mu;
        s_mu = mu;
        s_rinv = rsqrtf(var + EPSV);
    }
    __syncthreads();
    const float mu = s_mu, rinv = s_rinv;
    float4 gg = *(const float4*)&gam[tid * 4];
    float4 bb = *(const float4*)&bet[tid * 4];
    float4 o;
    o.x = (v.x - mu) * rinv * gg.x + bb.x;
    o.y = (v.y - mu) * rinv * gg.y + bb.y;
    o.z = (v.z - mu) * rinv * gg.z + bb.z;
    o.w = (v.w - mu) * rinv * gg.w + bb.w;
    *(float4*)&out[(size_t)r * DIM + tid * 4] = o;
}

// ------------------------- launch -------------------------
extern "C" void kernel_launch(void* const* d_in, const int* in_sizes, int n_in,
                              void* d_out, int out_size)
{
    const float* text   = (const float*)d_in[0];
    const float* vision = (const float*)d_in[1];
    const float* ipw    = (const float*)d_in[2];
    const float* ipb    = (const float*)d_in[3];
    const float* outw   = (const float*)d_in[4];
    const float* outb   = (const float*)d_in[5];
    const float* lng    = (const float*)d_in[6];
    const float* lnb    = (const float*)d_in[7];

    float* out   = (float*)d_out;
    float* attnw = out + (size_t)MQ * DIM;

    float* attp;
    cudaGetSymbolAddress((void**)&attp, g_att);

    __nv_bfloat16 *tAhi, *tAlo, *tVhi, *tVlo, *tWhi, *tWlo, *tOhi, *tOlo;
    __nv_bfloat16 *Qhi, *Qlo, *Khi, *Klo, *Vhi, *Vlo, *Chi, *Clo;
    cudaGetSymbolAddress((void**)&tAhi, g_tAhi); cudaGetSymbolAddress((void**)&tAlo, g_tAlo);
    cudaGetSymbolAddress((void**)&tVhi, g_tVhi); cudaGetSymbolAddress((void**)&tVlo, g_tVlo);
    cudaGetSymbolAddress((void**)&tWhi, g_tWhi); cudaGetSymbolAddress((void**)&tWlo, g_tWlo);
    cudaGetSymbolAddress((void**)&tOhi, g_tOhi); cudaGetSymbolAddress((void**)&tOlo, g_tOlo);
    cudaGetSymbolAddress((void**)&Qhi, g_Qhi); cudaGetSymbolAddress((void**)&Qlo, g_Qlo);
    cudaGetSymbolAddress((void**)&Khi, g_Khi); cudaGetSymbolAddress((void**)&Klo, g_Klo);
    cudaGetSymbolAddress((void**)&Vhi, g_Vhi); cudaGetSymbolAddress((void**)&Vlo, g_Vlo);
    cudaGetSymbolAddress((void**)&Chi, g_Chi); cudaGetSymbolAddress((void**)&Clo, g_Clo);

    cudaFuncSetAttribute(attn_mma, cudaFuncAttributeMaxDynamicSharedMemorySize, ATTN_SMEM);
    cudaFuncSetAttribute(gemm_mma<0>, cudaFuncAttributeMaxDynamicSharedMemorySize, GSM_TOTAL);
    cudaFuncSetAttribute(gemm_mma<1>, cudaFuncAttributeMaxDynamicSharedMemorySize, GSM_TOTAL);
    cudaFuncSetAttribute(gemm_mma<2>, cudaFuncAttributeMaxDynamicSharedMemorySize, GSM_TOTAL);

    // fp32 -> bf16 hi/lo splits (inputs + weights)
    int n4;
    n4 = (MQ * DIM) / 4;
    cvt_pair<<<(n4 + 255) / 256, 256>>>((const float4*)text, (__nv_bfloat162*)tAhi, (__nv_bfloat162*)tAlo, n4);
    n4 = (MK * DIM) / 4;
    cvt_pair<<<(n4 + 255) / 256, 256>>>((const float4*)vision, (__nv_bfloat162*)tVhi, (__nv_bfloat162*)tVlo, n4);
    n4 = (3 * DIM * DIM) / 4;
    cvt_pair<<<(n4 + 255) / 256, 256>>>((const float4*)ipw, (__nv_bfloat162*)tWhi, (__nv_bfloat162*)tWlo, n4);
    n4 = (DIM * DIM) / 4;
    cvt_pair<<<(n4 + 255) / 256, 256>>>((const float4*)outw, (__nv_bfloat162*)tOhi, (__nv_bfloat162*)tOlo, n4);

    // Q (scaled, split) = 0.125*(text @ Wq^T + bq)
    gemm_mma<1><<<dim3(DIM / 128, MQ / 128), 256, GSM_TOTAL>>>(
        tAhi, tAlo, tWhi, tWlo, ipb, nullptr, nullptr, Qhi, Qlo, nullptr, nullptr, MQ, DIM, DIM);
    // [K|V] (split) = vision @ [Wk|Wv]^T + [bk|bv]
    gemm_mma<2><<<dim3(2 * DIM / 128, MK / 128), 256, GSM_TOTAL>>>(
        tVhi, tVlo, tWhi + (size_t)DIM * DIM, tWlo + (size_t)DIM * DIM,
        ipb + DIM, nullptr, nullptr, Khi, Klo, Vhi, Vlo, MK, 2 * DIM, DIM);
    // attention -> attnw + ctx (split)
    attn_mma<<<NB * (LQ / 32), 256, ATTN_SMEM>>>(attnw);
    // attended = ctx @ out_w^T + out_b + text
    gemm_mma<0><<<dim3(DIM / 128, MQ / 128), 256, GSM_TOTAL>>>(
        Chi, Clo, tOhi, tOlo, outb, text, attp, nullptr, nullptr, nullptr, nullptr, MQ, DIM, DIM);
    // layernorm
    ln_kernel<<<MQ, 256>>>(attp, lng, lnb, out);
}

// round 5
// speedup vs baseline: 2.5653x; 1.2607x over previous
#include <cuda_runtime.h>
#include <cuda_bf16.h>
#include <cstdint>
#include <cstddef>

#define DIM 1024
#define NH 16
#define HD 64
#define NB 8
#define LQ 512
#define LKK 1024
#define MQ (NB*LQ)      // 4096
#define MK (NB*LKK)     // 8192
#define EPSV 1e-5f
#define QSCALE 0.125f

// ------------------------- scratch -------------------------
__device__ float g_att[(size_t)MQ * DIM];

__device__ __nv_bfloat16 g_tAhi[(size_t)MQ * DIM],  g_tAlo[(size_t)MQ * DIM];
__device__ __nv_bfloat16 g_tVhi[(size_t)MK * DIM],  g_tVlo[(size_t)MK * DIM];
__device__ __nv_bfloat16 g_tWhi[(size_t)3*DIM*DIM], g_tWlo[(size_t)3*DIM*DIM];
__device__ __nv_bfloat16 g_tOhi[(size_t)DIM*DIM],   g_tOlo[(size_t)DIM*DIM];
__device__ __nv_bfloat16 g_Qhi[(size_t)MQ * DIM],   g_Qlo[(size_t)MQ * DIM];
__device__ __nv_bfloat16 g_Khi[(size_t)MK * DIM],   g_Klo[(size_t)MK * DIM];
__device__ __nv_bfloat16 g_Vhi[(size_t)MK * DIM],   g_Vlo[(size_t)MK * DIM];
__device__ __nv_bfloat16 g_Chi[(size_t)MQ * DIM],   g_Clo[(size_t)MQ * DIM];

// ------------------------- helpers -------------------------
__device__ __forceinline__ uint32_t smem_to_u32(const void* p) {
    uint32_t a;
    asm("{ .reg .u64 t; cvta.to.shared.u64 t, %1; cvt.u32.u64 %0, t; }" : "=r"(a) : "l"(p));
    return a;
}
__device__ __forceinline__ void ldsm_x4(uint32_t* r, uint32_t addr) {
    asm volatile("ldmatrix.sync.aligned.m8n8.x4.shared.b16 {%0,%1,%2,%3}, [%4];"
        : "=r"(r[0]), "=r"(r[1]), "=r"(r[2]), "=r"(r[3]) : "r"(addr));
}
__device__ __forceinline__ void ldsm_x4_t(uint32_t* r, uint32_t addr) {
    asm volatile("ldmatrix.sync.aligned.m8n8.x4.trans.shared.b16 {%0,%1,%2,%3}, [%4];"
        : "=r"(r[0]), "=r"(r[1]), "=r"(r[2]), "=r"(r[3]) : "r"(addr));
}
__device__ __forceinline__ void mma16816(float* d, const uint32_t* a, const uint32_t* b) {
    asm volatile("mma.sync.aligned.m16n8k16.row.col.f32.bf16.bf16.f32 "
        "{%0,%1,%2,%3}, {%4,%5,%6,%7}, {%8,%9}, {%0,%1,%2,%3};"
        : "+f"(d[0]), "+f"(d[1]), "+f"(d[2]), "+f"(d[3])
        : "r"(a[0]), "r"(a[1]), "r"(a[2]), "r"(a[3]), "r"(b[0]), "r"(b[1]));
}
__device__ __forceinline__ void split2(float a, float b, uint32_t& hi, uint32_t& lo) {
    __nv_bfloat162 h = __floats2bfloat162_rn(a, b);
    __nv_bfloat162 l = __floats2bfloat162_rn(a - __low2float(h), b - __high2float(h));
    hi = *(uint32_t*)&h; lo = *(uint32_t*)&l;
}
__device__ __forceinline__ void cp16(uint32_t saddr, const void* g) {
    asm volatile("cp.async.cg.shared.global [%0], [%1], 16;" :: "r"(saddr), "l"(g));
}
#define CP_COMMIT() asm volatile("cp.async.commit_group;" ::: "memory")
#define CP_WAIT0()  asm volatile("cp.async.wait_group 0;" ::: "memory")

// ------------------------- fp32 -> (bf16 hi, bf16 lo) split -------------------------
__global__ __launch_bounds__(256) void cvt_pair(const float4* __restrict__ x,
                                                __nv_bfloat162* __restrict__ hi,
                                                __nv_bfloat162* __restrict__ lo, int n4)
{
    int i = blockIdx.x * blockDim.x + threadIdx.x;
    if (i >= n4) return;
    float4 v = x[i];
    __nv_bfloat162 hA = __floats2bfloat162_rn(v.x, v.y);
    __nv_bfloat162 hB = __floats2bfloat162_rn(v.z, v.w);
    __nv_bfloat162 lA = __floats2bfloat162_rn(v.x - __low2float(hA), v.y - __high2float(hA));
    __nv_bfloat162 lB = __floats2bfloat162_rn(v.z - __low2float(hB), v.w - __high2float(hB));
    hi[2 * i] = hA; hi[2 * i + 1] = hB;
    lo[2 * i] = lA; lo[2 * i + 1] = lB;
}

// ------------------------- mma.sync bf16x3 GEMM (cp.async double-buffered) -------------------------
// KC=32; tile per matrix per buf: 128 rows x 64B = 8KB; 4 matrices x 2 bufs = 64KB.
// Row layout: 64B/row, slot s (16B) at phys row*64 + ((s<<4) ^ (((row>>1)&3)<<4)).
#define GT_TILE 8192
#define GSM_TOTAL (8 * GT_TILE)

template<int MODE>
__global__ __launch_bounds__(256) void gemm_mma(
    const __nv_bfloat16* __restrict__ Ahi, const __nv_bfloat16* __restrict__ Alo,
    const __nv_bfloat16* __restrict__ Whi, const __nv_bfloat16* __restrict__ Wlo,
    const float* __restrict__ bias, const float* __restrict__ res,
    float* __restrict__ C,
    __nv_bfloat16* __restrict__ h0, __nv_bfloat16* __restrict__ l0,
    __nv_bfloat16* __restrict__ h1, __nv_bfloat16* __restrict__ l1,
    int M, int N, int K)
{
    extern __shared__ char sm[];
    const uint32_t sb = smem_to_u32(sm);

    const int tid  = threadIdx.x;
    const int wid  = tid >> 5;
    const int lane = tid & 31;
    const int bm = blockIdx.y * 128;
    const int bn = blockIdx.x * 128;
    const int m0 = (wid >> 2) * 64;
    const int n0 = (wid & 3) * 32;

    // loader slots: 2 per tile per thread
    int lrow[2], lsl[2], loff[2];
#pragma unroll
    for (int i = 0; i < 2; i++) {
        int u = tid + i * 256;
        lrow[i] = u >> 2;
        lsl[i]  = u & 3;
        loff[i] = lrow[i] * 64 + ((lsl[i] << 4) ^ (((lrow[i] >> 1) & 3) << 4));
    }

    const int arow_l = lane & 15;
    const int a_hi   = lane >> 4;           // slot add within ks
    const int brow_l = (lane & 7) + ((lane & 16) ? 8 : 0);
    const int b_hi   = (lane & 8) ? 1 : 0;
    const int gid = lane >> 2, tig = lane & 3;

    float acc[4][4][4];
#pragma unroll
    for (int i = 0; i < 4; i++)
#pragma unroll
        for (int j = 0; j < 4; j++)
#pragma unroll
            for (int l = 0; l < 4; l++) acc[i][j][l] = 0.f;

    const int nch = K >> 5;

    // prologue: chunk 0 -> buf 0
    {
        const uint32_t base = sb;
#pragma unroll
        for (int i = 0; i < 2; i++) {
            const int col = lsl[i] * 8;
            cp16(base + loff[i],               Ahi + (size_t)(bm + lrow[i]) * K + col);
            cp16(base + GT_TILE + loff[i],     Alo + (size_t)(bm + lrow[i]) * K + col);
            cp16(base + 2 * GT_TILE + loff[i], Whi + (size_t)(bn + lrow[i]) * K + col);
            cp16(base + 3 * GT_TILE + loff[i], Wlo + (size_t)(bn + lrow[i]) * K + col);
        }
        CP_COMMIT();
    }

    for (int c = 0; c < nch; c++) {
        CP_WAIT0();
        __syncthreads();
        if (c + 1 < nch) {
            const uint32_t base = sb + ((c + 1) & 1) * 4 * GT_TILE;
            const int coff = (c + 1) * 32;
#pragma unroll
            for (int i = 0; i < 2; i++) {
                const int col = coff + lsl[i] * 8;
                cp16(base + loff[i],               Ahi + (size_t)(bm + lrow[i]) * K + col);
                cp16(base + GT_TILE + loff[i],     Alo + (size_t)(bm + lrow[i]) * K + col);
                cp16(base + 2 * GT_TILE + loff[i], Whi + (size_t)(bn + lrow[i]) * K + col);
                cp16(base + 3 * GT_TILE + loff[i], Wlo + (size_t)(bn + lrow[i]) * K + col);
            }
            CP_COMMIT();
        }
        const uint32_t tb = sb + (c & 1) * 4 * GT_TILE;
#pragma unroll
        for (int ks = 0; ks < 2; ks++) {
            uint32_t ah[4][4], al[4][4];
#pragma unroll
            for (int mf = 0; mf < 4; mf++) {
                const int row = m0 + mf * 16 + arow_l;
                const int sl  = ks * 2 + a_hi;
                const uint32_t ad = tb + row * 64 + ((sl << 4) ^ (((row >> 1) & 3) << 4));
                ldsm_x4(ah[mf], ad);
                ldsm_x4(al[mf], ad + GT_TILE);
            }
            uint32_t bh[2][4], bl[2][4];
#pragma unroll
            for (int np = 0; np < 2; np++) {
                const int row = n0 + np * 16 + brow_l;
                const int sl  = ks * 2 + b_hi;
                const uint32_t ad = tb + 2 * GT_TILE + row * 64 + ((sl << 4) ^ (((row >> 1) & 3) << 4));
                ldsm_x4(bh[np], ad);
                ldsm_x4(bl[np], ad + GT_TILE);
            }
#pragma unroll
            for (int mf = 0; mf < 4; mf++)
#pragma unroll
                for (int np = 0; np < 2; np++)
#pragma unroll
                    for (int half = 0; half < 2; half++) {
                        float* d = acc[mf][np * 2 + half];
                        mma16816(d, ah[mf], &bh[np][half * 2]);
                        mma16816(d, ah[mf], &bl[np][half * 2]);
                        mma16816(d, al[mf], &bh[np][half * 2]);
                    }
        }
    }

    // ---- epilogue ----
#pragma unroll
    for (int mf = 0; mf < 4; mf++) {
        const int mrow0 = bm + m0 + mf * 16 + gid;
#pragma unroll
        for (int nf = 0; nf < 4; nf++) {
            const int col = bn + n0 + nf * 8 + tig * 2;
            const float2 bia = *(const float2*)&bias[col];
            float* d = acc[mf][nf];
            float v00 = d[0] + bia.x, v01 = d[1] + bia.y;
            float v10 = d[2] + bia.x, v11 = d[3] + bia.y;
            if (MODE == 0) {
                const size_t i0 = (size_t)mrow0 * N + col;
                const size_t i1 = (size_t)(mrow0 + 8) * N + col;
                if (res) {
                    float2 r0 = *(const float2*)&res[i0];
                    float2 r1 = *(const float2*)&res[i1];
                    v00 += r0.x; v01 += r0.y; v10 += r1.x; v11 += r1.y;
                }
                *(float2*)&C[i0] = make_float2(v00, v01);
                *(float2*)&C[i1] = make_float2(v10, v11);
            } else {
                if (MODE == 1) { v00 *= QSCALE; v01 *= QSCALE; v10 *= QSCALE; v11 *= QSCALE; }
                __nv_bfloat16 *H = h0, *L = l0;
                int cc = col;
                if (MODE == 2 && col >= DIM) { H = h1; L = l1; cc = col - DIM; }
                const size_t i0 = (size_t)mrow0 * DIM + cc;
                const size_t i1 = (size_t)(mrow0 + 8) * DIM + cc;
                uint32_t hh, ll;
                split2(v00, v01, hh, ll);
                *(uint32_t*)&H[i0] = hh; *(uint32_t*)&L[i0] = ll;
                split2(v10, v11, hh, ll);
                *(uint32_t*)&H[i1] = hh; *(uint32_t*)&L[i1] = ll;
            }
        }
    }
}

// ------------------------- tensor-core attention (cp.async pipelined) -------------------------
// smem: S 32x1024 f32 (reused in place as Phi/Plo), Q hi/lo, K/V chunk double buffer
#define SM_QH  131072
#define SM_QL  135168
#define SM_KV0 139264
#define KV_BUF 32768          // KH 16KB + KL 16KB per buffer
#define ATTN_SMEM (SM_KV0 + 2 * KV_BUF)   // 204800

__global__ __launch_bounds__(256) void attn_mma(float* __restrict__ attnw)
{
    extern __shared__ char sm[];
    float* S = (float*)sm;
    const uint32_t sb = smem_to_u32(sm);

    const int tid  = threadIdx.x;
    const int wid  = tid >> 5;
    const int lane = tid & 31;
    const int b  = blockIdx.x >> 4;
    const int q0 = (blockIdx.x & 15) << 5;

    const int ms  = (wid >> 2) * 16;
    const int ns  = (wid & 3) * 32;
    const int nv0 = (wid & 3) * 16;

    const int arow_l = lane & 15;
    const int axor   = (arow_l & 7) << 4;
    const int akb    = (lane >> 4) * 16;
    const int brow_l = (lane & 7) + ((lane & 16) ? 8 : 0);
    const int bxor   = (lane & 7) << 4;
    const int bkb    = (lane & 8) ? 16 : 0;
    const int gid = lane >> 2, tig = lane & 3;

    // K/V chunk loader slots (4 per tile per thread)
    int krow[4], koff_s[4], kcu[4];
#pragma unroll
    for (int i = 0; i < 4; i++) {
        int u = tid + i * 256;
        krow[i] = u >> 3;
        kcu[i]  = u & 7;
        koff_s[i] = krow[i] * 128 + ((kcu[i] * 16) ^ ((krow[i] & 7) << 4));
    }
    const int qrow = tid >> 3, qcu = tid & 7;
    const int qoff = qrow * 128 + ((qcu * 16) ^ ((qrow & 7) << 4));

    const int vkey_l = ((lane >> 3) & 1) * 8 + (lane & 7);
    const int vdim   = nv0 + ((lane >> 4) ? 8 : 0);

    for (int h = 0; h < NH; h++) {
        // ---- load Q hi/lo tile ----
        {
            size_t g = ((size_t)(b * LQ + q0 + qrow)) * DIM + h * HD + qcu * 8;
            *(uint4*)(sm + SM_QH + qoff) = *(const uint4*)(g_Qhi + g);
            *(uint4*)(sm + SM_QL + qoff) = *(const uint4*)(g_Qlo + g);
        }
        __syncthreads();   // Q visible; all warps done with prev head's V MMA

        // prologue: K chunk 0 -> buf 0
        {
            const uint32_t base = sb + SM_KV0;
#pragma unroll
            for (int i = 0; i < 4; i++) {
                size_t g = ((size_t)(b * LKK + krow[i])) * DIM + h * HD + kcu[i] * 8;
                cp16(base + koff_s[i],         g_Khi + g);
                cp16(base + 16384 + koff_s[i], g_Klo + g);
            }
            CP_COMMIT();
        }

        uint32_t qh[4][4], ql[4][4];
#pragma unroll
        for (int ks = 0; ks < 4; ks++) {
            int koff = (ks * 32 + akb) ^ axor;
            ldsm_x4(qh[ks], sb + SM_QH + (ms + arow_l) * 128 + koff);
            ldsm_x4(ql[ks], sb + SM_QL + (ms + arow_l) * 128 + koff);
        }

        // ---- scores ----
        for (int kc = 0; kc < 8; kc++) {
            CP_WAIT0();
            __syncthreads();
            if (kc < 7) {
                const uint32_t base = sb + SM_KV0 + ((kc + 1) & 1) * KV_BUF;
#pragma unroll
                for (int i = 0; i < 4; i++) {
                    size_t g = ((size_t)(b * LKK + (kc + 1) * 128 + krow[i])) * DIM + h * HD + kcu[i] * 8;
                    cp16(base + koff_s[i],         g_Khi + g);
                    cp16(base + 16384 + koff_s[i], g_Klo + g);
                }
                CP_COMMIT();
            }
            const uint32_t kb = sb + SM_KV0 + (kc & 1) * KV_BUF;
            float acc[4][4];
#pragma unroll
            for (int i = 0; i < 4; i++)
#pragma unroll
                for (int j = 0; j < 4; j++) acc[i][j] = 0.f;
#pragma unroll
            for (int ks = 0; ks < 4; ks++) {
                const int bkoff = (ks * 32 + bkb) ^ bxor;
                uint32_t bh[2][4], bl[2][4];
#pragma unroll
                for (int np = 0; np < 2; np++) {
                    const uint32_t ad = kb + (ns + np * 16 + brow_l) * 128 + bkoff;
                    ldsm_x4(bh[np], ad);
                    ldsm_x4(bl[np], ad + 16384);
                }
#pragma unroll
                for (int np = 0; np < 2; np++)
#pragma unroll
                    for (int half = 0; half < 2; half++) {
                        float* d = acc[np * 2 + half];
                        mma16816(d, qh[ks], &bh[np][half * 2]);
                        mma16816(d, qh[ks], &bl[np][half * 2]);
                        mma16816(d, ql[ks], &bh[np][half * 2]);
                    }
            }
#pragma unroll
            for (int nf = 0; nf < 4; nf++) {
                const int col = kc * 128 + ns + nf * 8 + tig * 2;
                *(float2*)&S[(ms + gid) * LKK + col]     = make_float2(acc[nf][0], acc[nf][1]);
                *(float2*)&S[(ms + gid + 8) * LKK + col] = make_float2(acc[nf][2], acc[nf][3]);
            }
        }
        __syncthreads();   // scores complete (all warps)

        // prologue: V chunk 0 -> buf 0 (overlaps softmax)
        {
            const uint32_t base = sb + SM_KV0;
#pragma unroll
            for (int i = 0; i < 4; i++) {
                size_t g = ((size_t)(b * LKK + krow[i])) * DIM + h * HD + kcu[i] * 8;
                cp16(base + koff_s[i],         g_Vhi + g);
                cp16(base + 16384 + koff_s[i], g_Vlo + g);
            }
            CP_COMMIT();
        }

        // ---- fused softmax + attn_weights + bf16 convert (register resident) ----
        {
            const float invh = 1.0f / NH;
            for (int r = wid * 4; r < wid * 4 + 4; r++) {
                float v[32];
                const float* src = &S[r * LKK + lane * 32];
#pragma unroll
                for (int j = 0; j < 8; j++) *(float4*)&v[j * 4] = *(const float4*)&src[j * 4];
                float mx = -1e30f;
#pragma unroll
                for (int j = 0; j < 32; j++) mx = fmaxf(mx, v[j]);
#pragma unroll
                for (int o = 16; o > 0; o >>= 1) mx = fmaxf(mx, __shfl_xor_sync(0xffffffffu, mx, o));
                float s = 0.f;
#pragma unroll
                for (int j = 0; j < 32; j++) { v[j] = __expf(v[j] - mx); s += v[j]; }
#pragma unroll
                for (int o = 16; o > 0; o >>= 1) s += __shfl_xor_sync(0xffffffffu, s, o);
                const float inv = 1.0f / s;
#pragma unroll
                for (int j = 0; j < 32; j++) v[j] *= inv;

                // attn_weights accumulation
                float* aw = attnw + ((size_t)(b * LQ + q0 + r)) * LKK + lane * 32;
                if (h == 0) {
#pragma unroll
                    for (int j = 0; j < 8; j++) {
                        float4 p = make_float4(v[j*4]*invh, v[j*4+1]*invh, v[j*4+2]*invh, v[j*4+3]*invh);
                        *(float4*)&aw[j * 4] = p;
                    }
                } else {
#pragma unroll
                    for (int j = 0; j < 8; j++) {
                        float4 o4 = *(const float4*)&aw[j * 4];
                        o4.x += v[j*4]*invh; o4.y += v[j*4+1]*invh;
                        o4.z += v[j*4+2]*invh; o4.w += v[j*4+3]*invh;
                        *(float4*)&aw[j * 4] = o4;
                    }
                }
                // in-place bf16 split: row r -> Phi [0,2048), Plo [2048,4096)
                char* rb = sm + r * 4096;
                const int sw = (r & 7) << 4;
#pragma unroll
                for (int j = 0; j < 4; j++) {
                    uint32_t h4[4], l4[4];
#pragma unroll
                    for (int p = 0; p < 4; p++)
                        split2(v[j * 8 + p * 2], v[j * 8 + p * 2 + 1], h4[p], l4[p]);
                    const int off = ((lane * 4 + j) * 16) ^ sw;
                    *(uint4*)(rb + off)        = *(uint4*)h4;
                    *(uint4*)(rb + 2048 + off) = *(uint4*)l4;
                }
            }
        }

        // ---- ctx = P @ V ----
        float cacc[2][4];
#pragma unroll
        for (int g = 0; g < 2; g++)
#pragma unroll
            for (int l = 0; l < 4; l++) cacc[g][l] = 0.f;

        for (int kc = 0; kc < 8; kc++) {
            CP_WAIT0();
            __syncthreads();   // V chunk landed + (kc==0) all conversions done
            if (kc < 7) {
                const uint32_t base = sb + SM_KV0 + ((kc + 1) & 1) * KV_BUF;
#pragma unroll
                for (int i = 0; i < 4; i++) {
                    size_t g = ((size_t)(b * LKK + (kc + 1) * 128 + krow[i])) * DIM + h * HD + kcu[i] * 8;
                    cp16(base + koff_s[i],         g_Vhi + g);
                    cp16(base + 16384 + koff_s[i], g_Vlo + g);
                }
                CP_COMMIT();
            }
            const uint32_t vb = sb + SM_KV0 + (kc & 1) * KV_BUF;
            const int mrow = ms + arow_l;
            const uint32_t pbase = sb + mrow * 4096;
            const int psw = (mrow & 7) << 4;
#pragma unroll
            for (int ks = 0; ks < 8; ks++) {
                const int poff = ((kc * 256 + ks * 32 + akb) ^ psw);
                uint32_t pah[4], pal[4];
                ldsm_x4(pah, pbase + poff);
                ldsm_x4(pal, pbase + 2048 + poff);
                const int key = ks * 16 + vkey_l;
                const uint32_t vaddr = vb + key * 128 + ((vdim * 2) ^ ((key & 7) << 4));
                uint32_t vh[4], vl[4];
                ldsm_x4_t(vh, vaddr);
                ldsm_x4_t(vl, vaddr + 16384);
#pragma unroll
                for (int g = 0; g < 2; g++) {
                    float* d = cacc[g];
                    mma16816(d, pah, &vh[g * 2]);
                    mma16816(d, pah, &vl[g * 2]);
                    mma16816(d, pal, &vh[g * 2]);
                }
            }
        }
        // ---- write ctx as bf16 hi/lo ----
#pragma unroll
        for (int g = 0; g < 2; g++) {
            const int col = h * HD + nv0 + g * 8 + tig * 2;
            const size_t i0 = ((size_t)(b * LQ + q0 + ms + gid)) * DIM + col;
            const size_t i1 = ((size_t)(b * LQ + q0 + ms + gid + 8)) * DIM + col;
            uint32_t hh, ll;
            split2(cacc[g][0], cacc[g][1], hh, ll);
            *(uint32_t*)&g_Chi[i0] = hh; *(uint32_t*)&g_Clo[i0] = ll;
            split2(cacc[g][2], cacc[g][3], hh, ll);
            *(uint32_t*)&g_Chi[i1] = hh; *(uint32_t*)&g_Clo[i1] = ll;
        }
    }
}

// ------------------------- layernorm -------------------------
__global__ __launch_bounds__(256) void ln_kernel(
    const float* __restrict__ X, const float* __restrict__ gam,
    const float* __restrict__ bet, float* __restrict__ out)
{
    __shared__ float red[64];
    __shared__ float s_mu, s_rinv;
    const int r = blockIdx.x, tid = threadIdx.x;
    const float* x = X + (size_t)r * DIM;
    float4 v = *(const float4*)&x[tid * 4];
    float s  = v.x + v.y + v.z + v.w;
    float sq = v.x * v.x + v.y * v.y + v.z * v.z + v.w * v.w;
#pragma unroll
    for (int o = 16; o > 0; o >>= 1) {
        s  += __shfl_xor_sync(0xffffffffu, s, o);
        sq += __shfl_xor_sync(0xffffffffu, sq, o);
    }
    const int w = tid >> 5;
    if ((tid & 31) == 0) { red[w] = s; red[32 + w] = sq; }
    __syncthreads();
    if (tid == 0) {
        float S = 0, Q = 0;
        for (int i = 0; i < 8; i++) { S += red[i]; Q += red[32 + i]; }
        float mu = S * (1.0f / DIM);
        float var = Q * (1.0f / DIM) - mu * mu;
        s_mu = mu;
        s_rinv = rsqrtf(var + EPSV);
    }
    __syncthreads();
    const float mu = s_mu, rinv = s_rinv;
    float4 gg = *(const float4*)&gam[tid * 4];
    float4 bb = *(const float4*)&bet[tid * 4];
    float4 o;
    o.x = (v.x - mu) * rinv * gg.x + bb.x;
    o.y = (v.y - mu) * rinv * gg.y + bb.y;
    o.z = (v.z - mu) * rinv * gg.z + bb.z;
    o.w = (v.w - mu) * rinv * gg.w + bb.w;
    *(float4*)&out[(size_t)r * DIM + tid * 4] = o;
}

// ------------------------- launch -------------------------
extern "C" void kernel_launch(void* const* d_in, const int* in_sizes, int n_in,
                              void* d_out, int out_size)
{
    const float* text   = (const float*)d_in[0];
    const float* vision = (const float*)d_in[1];
    const float* ipw    = (const float*)d_in[2];
    const float* ipb    = (const float*)d_in[3];
    const float* outw   = (const float*)d_in[4];
    const float* outb   = (const float*)d_in[5];
    const float* lng    = (const float*)d_in[6];
    const float* lnb    = (const float*)d_in[7];

    float* out   = (float*)d_out;
    float* attnw = out + (size_t)MQ * DIM;

    float* attp;
    cudaGetSymbolAddress((void**)&attp, g_att);

    __nv_bfloat16 *tAhi, *tAlo, *tVhi, *tVlo, *tWhi, *tWlo, *tOhi, *tOlo;
    __nv_bfloat16 *Qhi, *Qlo, *Khi, *Klo, *Vhi, *Vlo, *Chi, *Clo;
    cudaGetSymbolAddress((void**)&tAhi, g_tAhi); cudaGetSymbolAddress((void**)&tAlo, g_tAlo);
    cudaGetSymbolAddress((void**)&tVhi, g_tVhi); cudaGetSymbolAddress((void**)&tVlo, g_tVlo);
    cudaGetSymbolAddress((void**)&tWhi, g_tWhi); cudaGetSymbolAddress((void**)&tWlo, g_tWlo);
    cudaGetSymbolAddress((void**)&tOhi, g_tOhi); cudaGetSymbolAddress((void**)&tOlo, g_tOlo);
    cudaGetSymbolAddress((void**)&Qhi, g_Qhi); cudaGetSymbolAddress((void**)&Qlo, g_Qlo);
    cudaGetSymbolAddress((void**)&Khi, g_Khi); cudaGetSymbolAddress((void**)&Klo, g_Klo);
    cudaGetSymbolAddress((void**)&Vhi, g_Vhi); cudaGetSymbolAddress((void**)&Vlo, g_Vlo);
    cudaGetSymbolAddress((void**)&Chi, g_Chi); cudaGetSymbolAddress((void**)&Clo, g_Clo);

    cudaFuncSetAttribute(attn_mma, cudaFuncAttributeMaxDynamicSharedMemorySize, ATTN_SMEM);
    cudaFuncSetAttribute(gemm_mma<0>, cudaFuncAttributeMaxDynamicSharedMemorySize, GSM_TOTAL);
    cudaFuncSetAttribute(gemm_mma<1>, cudaFuncAttributeMaxDynamicSharedMemorySize, GSM_TOTAL);
    cudaFuncSetAttribute(gemm_mma<2>, cudaFuncAttributeMaxDynamicSharedMemorySize, GSM_TOTAL);

    int n4;
    n4 = (MQ * DIM) / 4;
    cvt_pair<<<(n4 + 255) / 256, 256>>>((const float4*)text, (__nv_bfloat162*)tAhi, (__nv_bfloat162*)tAlo, n4);
    n4 = (MK * DIM) / 4;
    cvt_pair<<<(n4 + 255) / 256, 256>>>((const float4*)vision, (__nv_bfloat162*)tVhi, (__nv_bfloat162*)tVlo, n4);
    n4 = (3 * DIM * DIM) / 4;
    cvt_pair<<<(n4 + 255) / 256, 256>>>((const float4*)ipw, (__nv_bfloat162*)tWhi, (__nv_bfloat162*)tWlo, n4);
    n4 = (DIM * DIM) / 4;
    cvt_pair<<<(n4 + 255) / 256, 256>>>((const float4*)outw, (__nv_bfloat162*)tOhi, (__nv_bfloat162*)tOlo, n4);

    gemm_mma<1><<<dim3(DIM / 128, MQ / 128), 256, GSM_TOTAL>>>(
        tAhi, tAlo, tWhi, tWlo, ipb, nullptr, nullptr, Qhi, Qlo, nullptr, nullptr, MQ, DIM, DIM);
    gemm_mma<2><<<dim3(2 * DIM / 128, MK / 128), 256, GSM_TOTAL>>>(
        tVhi, tVlo, tWhi + (size_t)DIM * DIM, tWlo + (size_t)DIM * DIM,
        ipb + DIM, nullptr, nullptr, Khi, Klo, Vhi, Vlo, MK, 2 * DIM, DIM);
    attn_mma<<<NB * (LQ / 32), 256, ATTN_SMEM>>>(attnw);
    gemm_mma<0><<<dim3(DIM / 128, MQ / 128), 256, GSM_TOTAL>>>(
        Chi, Clo, tOhi, tOlo, outb, text, attp, nullptr, nullptr, nullptr, nullptr, MQ, DIM, DIM);
    ln_kernel<<<MQ, 256>>>(attp, lng, lnb, out);
}

// round 6
// speedup vs baseline: 3.0907x; 1.2048x over previous
#include <cuda_runtime.h>
#include <cuda_fp16.h>
#include <cstdint>
#include <cstddef>

#define DIM 1024
#define NH 16
#define HD 64
#define NB 8
#define LQ 512
#define LKK 1024
#define MQ (NB*LQ)      // 4096
#define MK (NB*LKK)     // 8192
#define EPSV 1e-5f
#define QSCALE 0.125f
#define WUP 32.0f
#define WINV (1.0f/32.0f)

// ------------------------- scratch -------------------------
__device__ float g_att[(size_t)MQ * DIM];

__device__ __half g_tAhi[(size_t)MQ * DIM];                               // text hi
__device__ __half g_tVhi[(size_t)MK * DIM];                               // vision hi
__device__ __half g_tWhi[(size_t)3*DIM*DIM], g_tWlo[(size_t)3*DIM*DIM];  // 32*in_proj_w
__device__ __half g_tOhi[(size_t)DIM*DIM],   g_tOlo[(size_t)DIM*DIM];    // 32*out_w
__device__ __half g_Qhi[(size_t)MQ * DIM];                                // scaled Q
__device__ __half g_Khi[(size_t)MK * DIM],   g_Klo[(size_t)MK * DIM];
__device__ __half g_Vhi[(size_t)MK * DIM],   g_Vlo[(size_t)MK * DIM];
__device__ __half g_Chi[(size_t)MQ * DIM];                                // ctx hi

// ------------------------- helpers -------------------------
__device__ __forceinline__ uint32_t smem_to_u32(const void* p) {
    uint32_t a;
    asm("{ .reg .u64 t; cvta.to.shared.u64 t, %1; cvt.u32.u64 %0, t; }" : "=r"(a) : "l"(p));
    return a;
}
__device__ __forceinline__ void ldsm_x4(uint32_t* r, uint32_t addr) {
    asm volatile("ldmatrix.sync.aligned.m8n8.x4.shared.b16 {%0,%1,%2,%3}, [%4];"
        : "=r"(r[0]), "=r"(r[1]), "=r"(r[2]), "=r"(r[3]) : "r"(addr));
}
__device__ __forceinline__ void ldsm_x4_t(uint32_t* r, uint32_t addr) {
    asm volatile("ldmatrix.sync.aligned.m8n8.x4.trans.shared.b16 {%0,%1,%2,%3}, [%4];"
        : "=r"(r[0]), "=r"(r[1]), "=r"(r[2]), "=r"(r[3]) : "r"(addr));
}
__device__ __forceinline__ void mma16816(float* d, const uint32_t* a, const uint32_t* b) {
    asm volatile("mma.sync.aligned.m16n8k16.row.col.f32.f16.f16.f32 "
        "{%0,%1,%2,%3}, {%4,%5,%6,%7}, {%8,%9}, {%0,%1,%2,%3};"
        : "+f"(d[0]), "+f"(d[1]), "+f"(d[2]), "+f"(d[3])
        : "r"(a[0]), "r"(a[1]), "r"(a[2]), "r"(a[3]), "r"(b[0]), "r"(b[1]));
}
__device__ __forceinline__ uint32_t h2bits(float a, float b) {
    __half2 h = __floats2half2_rn(a, b);
    return *(uint32_t*)&h;
}
__device__ __forceinline__ void split2h(float a, float b, uint32_t& hi, uint32_t& lo) {
    __half2 h = __floats2half2_rn(a, b);
    float2 hf = __half22float2(h);
    __half2 l = __floats2half2_rn(a - hf.x, b - hf.y);
    hi = *(uint32_t*)&h; lo = *(uint32_t*)&l;
}
__device__ __forceinline__ void cp16(uint32_t saddr, const void* g) {
    asm volatile("cp.async.cg.shared.global [%0], [%1], 16;" :: "r"(saddr), "l"(g));
}
#define CP_COMMIT() asm volatile("cp.async.commit_group;" ::: "memory")
#define CP_WAIT0()  asm volatile("cp.async.wait_group 0;" ::: "memory")

// ------------------------- conversions -------------------------
__global__ __launch_bounds__(256) void cvt_hi(const float4* __restrict__ x,
                                              uint32_t* __restrict__ hi, int n4)
{
    int i = blockIdx.x * blockDim.x + threadIdx.x;
    if (i >= n4) return;
    float4 v = x[i];
    hi[2 * i]     = h2bits(v.x, v.y);
    hi[2 * i + 1] = h2bits(v.z, v.w);
}

__global__ __launch_bounds__(256) void cvt_pair_h(const float4* __restrict__ x,
                                                  uint32_t* __restrict__ hi,
                                                  uint32_t* __restrict__ lo,
                                                  float scale, int n4)
{
    int i = blockIdx.x * blockDim.x + threadIdx.x;
    if (i >= n4) return;
    float4 v = x[i];
    uint32_t h0, l0, h1, l1;
    split2h(v.x * scale, v.y * scale, h0, l0);
    split2h(v.z * scale, v.w * scale, h1, l1);
    hi[2 * i] = h0; hi[2 * i + 1] = h1;
    lo[2 * i] = l0; lo[2 * i + 1] = l1;
}

// ------------------------- mma.sync fp16 2-pass GEMM -------------------------
// C = A @ W^T (+bias/res). A hi-only fp16; W stored as 32*W hi/lo fp16.
// acc scaled back by WINV in epilogue. KC=32; 3 tiles x 2 buffers = 48 KB.
#define GT_TILE 8192
#define GSM_TOTAL (6 * GT_TILE)

template<int MODE>
__global__ __launch_bounds__(256) void gemm_mma(
    const __half* __restrict__ Ahi,
    const __half* __restrict__ Whi, const __half* __restrict__ Wlo,
    const float* __restrict__ bias, const float* __restrict__ res,
    float* __restrict__ C,
    __half* __restrict__ h0, __half* __restrict__ l0,
    __half* __restrict__ h1, __half* __restrict__ l1,
    int M, int N, int K)
{
    extern __shared__ char sm[];
    const uint32_t sb = smem_to_u32(sm);

    const int tid  = threadIdx.x;
    const int wid  = tid >> 5;
    const int lane = tid & 31;
    const int bm = blockIdx.y * 128;
    const int bn = blockIdx.x * 128;
    const int m0 = (wid >> 2) * 64;
    const int n0 = (wid & 3) * 32;

    int lrow[2], lsl[2], loff[2];
#pragma unroll
    for (int i = 0; i < 2; i++) {
        int u = tid + i * 256;
        lrow[i] = u >> 2;
        lsl[i]  = u & 3;
        loff[i] = lrow[i] * 64 + ((lsl[i] << 4) ^ (((lrow[i] >> 1) & 3) << 4));
    }

    const int arow_l = lane & 15;
    const int a_hi   = lane >> 4;
    const int brow_l = (lane & 7) + ((lane & 16) ? 8 : 0);
    const int b_hi   = (lane & 8) ? 1 : 0;
    const int gid = lane >> 2, tig = lane & 3;

    float acc[4][4][4];
#pragma unroll
    for (int i = 0; i < 4; i++)
#pragma unroll
        for (int j = 0; j < 4; j++)
#pragma unroll
            for (int l = 0; l < 4; l++) acc[i][j][l] = 0.f;

    const int nch = K >> 5;

    {
        const uint32_t base = sb;
#pragma unroll
        for (int i = 0; i < 2; i++) {
            const int col = lsl[i] * 8;
            cp16(base + loff[i],               Ahi + (size_t)(bm + lrow[i]) * K + col);
            cp16(base + GT_TILE + loff[i],     Whi + (size_t)(bn + lrow[i]) * K + col);
            cp16(base + 2 * GT_TILE + loff[i], Wlo + (size_t)(bn + lrow[i]) * K + col);
        }
        CP_COMMIT();
    }

    for (int c = 0; c < nch; c++) {
        CP_WAIT0();
        __syncthreads();
        if (c + 1 < nch) {
            const uint32_t base = sb + ((c + 1) & 1) * 3 * GT_TILE;
            const int coff = (c + 1) * 32;
#pragma unroll
            for (int i = 0; i < 2; i++) {
                const int col = coff + lsl[i] * 8;
                cp16(base + loff[i],               Ahi + (size_t)(bm + lrow[i]) * K + col);
                cp16(base + GT_TILE + loff[i],     Whi + (size_t)(bn + lrow[i]) * K + col);
                cp16(base + 2 * GT_TILE + loff[i], Wlo + (size_t)(bn + lrow[i]) * K + col);
            }
            CP_COMMIT();
        }
        const uint32_t tb = sb + (c & 1) * 3 * GT_TILE;
#pragma unroll
        for (int ks = 0; ks < 2; ks++) {
            uint32_t ah[4][4];
#pragma unroll
            for (int mf = 0; mf < 4; mf++) {
                const int row = m0 + mf * 16 + arow_l;
                const int sl  = ks * 2 + a_hi;
                ldsm_x4(ah[mf], tb + row * 64 + ((sl << 4) ^ (((row >> 1) & 3) << 4)));
            }
            uint32_t bh[2][4], bl[2][4];
#pragma unroll
            for (int np = 0; np < 2; np++) {
                const int row = n0 + np * 16 + brow_l;
                const int sl  = ks * 2 + b_hi;
                const uint32_t ad = tb + GT_TILE + row * 64 + ((sl << 4) ^ (((row >> 1) & 3) << 4));
                ldsm_x4(bh[np], ad);
                ldsm_x4(bl[np], ad + GT_TILE);
            }
#pragma unroll
            for (int mf = 0; mf < 4; mf++)
#pragma unroll
                for (int np = 0; np < 2; np++)
#pragma unroll
                    for (int half = 0; half < 2; half++) {
                        float* d = acc[mf][np * 2 + half];
                        mma16816(d, ah[mf], &bh[np][half * 2]);
                        mma16816(d, ah[mf], &bl[np][half * 2]);
                    }
        }
    }

    // ---- epilogue ----
#pragma unroll
    for (int mf = 0; mf < 4; mf++) {
        const int mrow0 = bm + m0 + mf * 16 + gid;
#pragma unroll
        for (int nf = 0; nf < 4; nf++) {
            const int col = bn + n0 + nf * 8 + tig * 2;
            const float2 bia = *(const float2*)&bias[col];
            float* d = acc[mf][nf];
            float v00 = d[0] * WINV + bia.x, v01 = d[1] * WINV + bia.y;
            float v10 = d[2] * WINV + bia.x, v11 = d[3] * WINV + bia.y;
            if (MODE == 0) {
                const size_t i0 = (size_t)mrow0 * N + col;
                const size_t i1 = (size_t)(mrow0 + 8) * N + col;
                if (res) {
                    float2 r0 = *(const float2*)&res[i0];
                    float2 r1 = *(const float2*)&res[i1];
                    v00 += r0.x; v01 += r0.y; v10 += r1.x; v11 += r1.y;
                }
                *(float2*)&C[i0] = make_float2(v00, v01);
                *(float2*)&C[i1] = make_float2(v10, v11);
            } else if (MODE == 1) {
                v00 *= QSCALE; v01 *= QSCALE; v10 *= QSCALE; v11 *= QSCALE;
                const size_t i0 = (size_t)mrow0 * DIM + col;
                const size_t i1 = (size_t)(mrow0 + 8) * DIM + col;
                *(uint32_t*)&h0[i0] = h2bits(v00, v01);
                *(uint32_t*)&h0[i1] = h2bits(v10, v11);
            } else {
                __half *H = h0, *L = l0;
                int cc = col;
                if (col >= DIM) { H = h1; L = l1; cc = col - DIM; }
                const size_t i0 = (size_t)mrow0 * DIM + cc;
                const size_t i1 = (size_t)(mrow0 + 8) * DIM + cc;
                uint32_t hh, ll;
                split2h(v00, v01, hh, ll);
                *(uint32_t*)&H[i0] = hh; *(uint32_t*)&L[i0] = ll;
                split2h(v10, v11, hh, ll);
                *(uint32_t*)&H[i1] = hh; *(uint32_t*)&L[i1] = ll;
            }
        }
    }
}

// ------------------------- tensor-core attention (fp16 2-pass) -------------------------
#define SM_QH  131072
#define SM_KV0 135168
#define KV_BUF 32768
#define ATTN_SMEM (SM_KV0 + 2 * KV_BUF)   // 200704

__global__ __launch_bounds__(256) void attn_mma(float* __restrict__ attnw)
{
    extern __shared__ char sm[];
    float* S = (float*)sm;
    const uint32_t sb = smem_to_u32(sm);

    const int tid  = threadIdx.x;
    const int wid  = tid >> 5;
    const int lane = tid & 31;
    const int b  = blockIdx.x >> 4;
    const int q0 = (blockIdx.x & 15) << 5;

    const int ms  = (wid >> 2) * 16;
    const int ns  = (wid & 3) * 32;
    const int nv0 = (wid & 3) * 16;

    const int arow_l = lane & 15;
    const int axor   = (arow_l & 7) << 4;
    const int akb    = (lane >> 4) * 16;
    const int brow_l = (lane & 7) + ((lane & 16) ? 8 : 0);
    const int bxor   = (lane & 7) << 4;
    const int bkb    = (lane & 8) ? 16 : 0;
    const int gid = lane >> 2, tig = lane & 3;

    int krow[4], koff_s[4], kcu[4];
#pragma unroll
    for (int i = 0; i < 4; i++) {
        int u = tid + i * 256;
        krow[i] = u >> 3;
        kcu[i]  = u & 7;
        koff_s[i] = krow[i] * 128 + ((kcu[i] * 16) ^ ((krow[i] & 7) << 4));
    }
    const int qrow = tid >> 3, qcu = tid & 7;
    const int qoff = qrow * 128 + ((qcu * 16) ^ ((qrow & 7) << 4));

    const int vkey_l = ((lane >> 3) & 1) * 8 + (lane & 7);
    const int vdim   = nv0 + ((lane >> 4) ? 8 : 0);

    for (int h = 0; h < NH; h++) {
        {
            size_t g = ((size_t)(b * LQ + q0 + qrow)) * DIM + h * HD + qcu * 8;
            *(uint4*)(sm + SM_QH + qoff) = *(const uint4*)(g_Qhi + g);
        }
        __syncthreads();

        // K chunk 0 -> buf 0
        {
            const uint32_t base = sb + SM_KV0;
#pragma unroll
            for (int i = 0; i < 4; i++) {
                size_t g = ((size_t)(b * LKK + krow[i])) * DIM + h * HD + kcu[i] * 8;
                cp16(base + koff_s[i],         g_Khi + g);
                cp16(base + 16384 + koff_s[i], g_Klo + g);
            }
            CP_COMMIT();
        }

        uint32_t qh[4][4];
#pragma unroll
        for (int ks = 0; ks < 4; ks++) {
            int koff = (ks * 32 + akb) ^ axor;
            ldsm_x4(qh[ks], sb + SM_QH + (ms + arow_l) * 128 + koff);
        }

        // ---- scores ----
        for (int kc = 0; kc < 8; kc++) {
            CP_WAIT0();
            __syncthreads();
            if (kc < 7) {
                const uint32_t base = sb + SM_KV0 + ((kc + 1) & 1) * KV_BUF;
#pragma unroll
                for (int i = 0; i < 4; i++) {
                    size_t g = ((size_t)(b * LKK + (kc + 1) * 128 + krow[i])) * DIM + h * HD + kcu[i] * 8;
                    cp16(base + koff_s[i],         g_Khi + g);
                    cp16(base + 16384 + koff_s[i], g_Klo + g);
                }
                CP_COMMIT();
            }
            const uint32_t kb = sb + SM_KV0 + (kc & 1) * KV_BUF;
            float acc[4][4];
#pragma unroll
            for (int i = 0; i < 4; i++)
#pragma unroll
                for (int j = 0; j < 4; j++) acc[i][j] = 0.f;
#pragma unroll
            for (int ks = 0; ks < 4; ks++) {
                const int bkoff = (ks * 32 + bkb) ^ bxor;
                uint32_t bh[2][4], bl[2][4];
#pragma unroll
                for (int np = 0; np < 2; np++) {
                    const uint32_t ad = kb + (ns + np * 16 + brow_l) * 128 + bkoff;
                    ldsm_x4(bh[np], ad);
                    ldsm_x4(bl[np], ad + 16384);
                }
#pragma unroll
                for (int np = 0; np < 2; np++)
#pragma unroll
                    for (int half = 0; half < 2; half++) {
                        float* d = acc[np * 2 + half];
                        mma16816(d, qh[ks], &bh[np][half * 2]);
                        mma16816(d, qh[ks], &bl[np][half * 2]);
                    }
            }
#pragma unroll
            for (int nf = 0; nf < 4; nf++) {
                const int col = kc * 128 + ns + nf * 8 + tig * 2;
                *(float2*)&S[(ms + gid) * LKK + col]     = make_float2(acc[nf][0], acc[nf][1]);
                *(float2*)&S[(ms + gid + 8) * LKK + col] = make_float2(acc[nf][2], acc[nf][3]);
            }
        }
        __syncthreads();

        // V chunk 0 -> buf 0 (overlaps softmax)
        {
            const uint32_t base = sb + SM_KV0;
#pragma unroll
            for (int i = 0; i < 4; i++) {
                size_t g = ((size_t)(b * LKK + krow[i])) * DIM + h * HD + kcu[i] * 8;
                cp16(base + koff_s[i],         g_Vhi + g);
                cp16(base + 16384 + koff_s[i], g_Vlo + g);
            }
            CP_COMMIT();
        }

        // ---- fused softmax + attnw + fp16 convert ----
        {
            const float invh = 1.0f / NH;
            for (int r = wid * 4; r < wid * 4 + 4; r++) {
                float v[32];
                const float* src = &S[r * LKK + lane * 32];
#pragma unroll
                for (int j = 0; j < 8; j++) *(float4*)&v[j * 4] = *(const float4*)&src[j * 4];
                float mx = -1e30f;
#pragma unroll
                for (int j = 0; j < 32; j++) mx = fmaxf(mx, v[j]);
#pragma unroll
                for (int o = 16; o > 0; o >>= 1) mx = fmaxf(mx, __shfl_xor_sync(0xffffffffu, mx, o));
                float s = 0.f;
#pragma unroll
                for (int j = 0; j < 32; j++) { v[j] = __expf(v[j] - mx); s += v[j]; }
#pragma unroll
                for (int o = 16; o > 0; o >>= 1) s += __shfl_xor_sync(0xffffffffu, s, o);
                const float inv = 1.0f / s;
#pragma unroll
                for (int j = 0; j < 32; j++) v[j] *= inv;

                float* aw = attnw + ((size_t)(b * LQ + q0 + r)) * LKK + lane * 32;
                if (h == 0) {
#pragma unroll
                    for (int j = 0; j < 8; j++) {
                        float4 p = make_float4(v[j*4]*invh, v[j*4+1]*invh, v[j*4+2]*invh, v[j*4+3]*invh);
                        *(float4*)&aw[j * 4] = p;
                    }
                } else {
#pragma unroll
                    for (int j = 0; j < 8; j++) {
                        float4 o4 = *(const float4*)&aw[j * 4];
                        o4.x += v[j*4]*invh; o4.y += v[j*4+1]*invh;
                        o4.z += v[j*4+2]*invh; o4.w += v[j*4+3]*invh;
                        *(float4*)&aw[j * 4] = o4;
                    }
                }
                // P hi-only fp16: row r -> bytes [0,2048) of rb
                char* rb = sm + r * 4096;
                const int sw = (r & 7) << 4;
#pragma unroll
                for (int j = 0; j < 4; j++) {
                    uint32_t h4[4];
#pragma unroll
                    for (int p = 0; p < 4; p++)
                        h4[p] = h2bits(v[j * 8 + p * 2], v[j * 8 + p * 2 + 1]);
                    const int off = ((lane * 4 + j) * 16) ^ sw;
                    *(uint4*)(rb + off) = *(uint4*)h4;
                }
            }
        }

        // ---- ctx = P @ V ----
        float cacc[2][4];
#pragma unroll
        for (int g = 0; g < 2; g++)
#pragma unroll
            for (int l = 0; l < 4; l++) cacc[g][l] = 0.f;

        for (int kc = 0; kc < 8; kc++) {
            CP_WAIT0();
            __syncthreads();
            if (kc < 7) {
                const uint32_t base = sb + SM_KV0 + ((kc + 1) & 1) * KV_BUF;
#pragma unroll
                for (int i = 0; i < 4; i++) {
                    size_t g = ((size_t)(b * LKK + (kc + 1) * 128 + krow[i])) * DIM + h * HD + kcu[i] * 8;
                    cp16(base + koff_s[i],         g_Vhi + g);
                    cp16(base + 16384 + koff_s[i], g_Vlo + g);
                }
                CP_COMMIT();
            }
            const uint32_t vb = sb + SM_KV0 + (kc & 1) * KV_BUF;
            const int mrow = ms + arow_l;
            const uint32_t pbase = sb + mrow * 4096;
            const int psw = (mrow & 7) << 4;
#pragma unroll
            for (int ks = 0; ks < 8; ks++) {
                const int poff = ((kc * 256 + ks * 32 + akb) ^ psw);
                uint32_t pah[4];
                ldsm_x4(pah, pbase + poff);
                const int key = ks * 16 + vkey_l;
                const uint32_t vaddr = vb + key * 128 + ((vdim * 2) ^ ((key & 7) << 4));
                uint32_t vh[4], vl[4];
                ldsm_x4_t(vh, vaddr);
                ldsm_x4_t(vl, vaddr + 16384);
#pragma unroll
                for (int g = 0; g < 2; g++) {
                    float* d = cacc[g];
                    mma16816(d, pah, &vh[g * 2]);
                    mma16816(d, pah, &vl[g * 2]);
                }
            }
        }
        // ---- write ctx hi fp16 ----
#pragma unroll
        for (int g = 0; g < 2; g++) {
            const int col = h * HD + nv0 + g * 8 + tig * 2;
            const size_t i0 = ((size_t)(b * LQ + q0 + ms + gid)) * DIM + col;
            const size_t i1 = ((size_t)(b * LQ + q0 + ms + gid + 8)) * DIM + col;
            *(uint32_t*)&g_Chi[i0] = h2bits(cacc[g][0], cacc[g][1]);
            *(uint32_t*)&g_Chi[i1] = h2bits(cacc[g][2], cacc[g][3]);
        }
    }
}

// ------------------------- layernorm -------------------------
__global__ __launch_bounds__(256) void ln_kernel(
    const float* __restrict__ X, const float* __restrict__ gam,
    const float* __restrict__ bet, float* __restrict__ out)
{
    __shared__ float red[64];
    __shared__ float s_mu, s_rinv;
    const int r = blockIdx.x, tid = threadIdx.x;
    const float* x = X + (size_t)r * DIM;
    float4 v = *(const float4*)&x[tid * 4];
    float s  = v.x + v.y + v.z + v.w;
    float sq = v.x * v.x + v.y * v.y + v.z * v.z + v.w * v.w;
#pragma unroll
    for (int o = 16; o > 0; o >>= 1) {
        s  += __shfl_xor_sync(0xffffffffu, s, o);
        sq += __shfl_xor_sync(0xffffffffu, sq, o);
    }
    const int w = tid >> 5;
    if ((tid & 31) == 0) { red[w] = s; red[32 + w] = sq; }
    __syncthreads();
    if (tid == 0) {
        float S = 0, Q = 0;
        for (int i = 0; i < 8; i++) { S += red[i]; Q += red[32 + i]; }
        float mu = S * (1.0f / DIM);
        float var = Q * (1.0f / DIM) - mu * mu;
        s_mu = mu;
        s_rinv = rsqrtf(var + EPSV);
    }
    __syncthreads();
    const float mu = s_mu, rinv = s_rinv;
    float4 gg = *(const float4*)&gam[tid * 4];
    float4 bb = *(const float4*)&bet[tid * 4];
    float4 o;
    o.x = (v.x - mu) * rinv * gg.x + bb.x;
    o.y = (v.y - mu) * rinv * gg.y + bb.y;
    o.z = (v.z - mu) * rinv * gg.z + bb.z;
    o.w = (v.w - mu) * rinv * gg.w + bb.w;
    *(float4*)&out[(size_t)r * DIM + tid * 4] = o;
}

// ------------------------- launch -------------------------
extern "C" void kernel_launch(void* const* d_in, const int* in_sizes, int n_in,
                              void* d_out, int out_size)
{
    const float* text   = (const float*)d_in[0];
    const float* vision = (const float*)d_in[1];
    const float* ipw    = (const float*)d_in[2];
    const float* ipb    = (const float*)d_in[3];
    const float* outw   = (const float*)d_in[4];
    const float* outb   = (const float*)d_in[5];
    const float* lng    = (const float*)d_in[6];
    const float* lnb    = (const float*)d_in[7];

    float* out   = (float*)d_out;
    float* attnw = out + (size_t)MQ * DIM;

    float* attp;
    cudaGetSymbolAddress((void**)&attp, g_att);

    __half *tAhi, *tVhi, *tWhi, *tWlo, *tOhi, *tOlo;
    __half *Qhi, *Khi, *Klo, *Vhi, *Vlo, *Chi;
    cudaGetSymbolAddress((void**)&tAhi, g_tAhi);
    cudaGetSymbolAddress((void**)&tVhi, g_tVhi);
    cudaGetSymbolAddress((void**)&tWhi, g_tWhi); cudaGetSymbolAddress((void**)&tWlo, g_tWlo);
    cudaGetSymbolAddress((void**)&tOhi, g_tOhi); cudaGetSymbolAddress((void**)&tOlo, g_tOlo);
    cudaGetSymbolAddress((void**)&Qhi, g_Qhi);
    cudaGetSymbolAddress((void**)&Khi, g_Khi); cudaGetSymbolAddress((void**)&Klo, g_Klo);
    cudaGetSymbolAddress((void**)&Vhi, g_Vhi); cudaGetSymbolAddress((void**)&Vlo, g_Vlo);
    cudaGetSymbolAddress((void**)&Chi, g_Chi);

    cudaFuncSetAttribute(attn_mma, cudaFuncAttributeMaxDynamicSharedMemorySize, ATTN_SMEM);
    cudaFuncSetAttribute(gemm_mma<0>, cudaFuncAttributeMaxDynamicSharedMemorySize, GSM_TOTAL);
    cudaFuncSetAttribute(gemm_mma<1>, cudaFuncAttributeMaxDynamicSharedMemorySize, GSM_TOTAL);
    cudaFuncSetAttribute(gemm_mma<2>, cudaFuncAttributeMaxDynamicSharedMemorySize, GSM_TOTAL);

    int n4;
    n4 = (MQ * DIM) / 4;
    cvt_hi<<<(n4 + 255) / 256, 256>>>((const float4*)text, (uint32_t*)tAhi, n4);
    n4 = (MK * DIM) / 4;
    cvt_hi<<<(n4 + 255) / 256, 256>>>((const float4*)vision, (uint32_t*)tVhi, n4);
    n4 = (3 * DIM * DIM) / 4;
    cvt_pair_h<<<(n4 + 255) / 256, 256>>>((const float4*)ipw, (uint32_t*)tWhi, (uint32_t*)tWlo, WUP, n4);
    n4 = (DIM * DIM) / 4;
    cvt_pair_h<<<(n4 + 255) / 256, 256>>>((const float4*)outw, (uint32_t*)tOhi, (uint32_t*)tOlo, WUP, n4);

    // Q (scaled fp16) = 0.125*(text @ Wq^T + bq)
    gemm_mma<1><<<dim3(DIM / 128, MQ / 128), 256, GSM_TOTAL>>>(
        tAhi, tWhi, tWlo, ipb, nullptr, nullptr, Qhi, nullptr, nullptr, nullptr, MQ, DIM, DIM);
    // [K|V] (hi/lo fp16) = vision @ [Wk|Wv]^T + [bk|bv]
    gemm_mma<2><<<dim3(2 * DIM / 128, MK / 128), 256, GSM_TOTAL>>>(
        tVhi, tWhi + (size_t)DIM * DIM, tWlo + (size_t)DIM * DIM,
        ipb + DIM, nullptr, nullptr, Khi, Klo, Vhi, Vlo, MK, 2 * DIM, DIM);
    // attention
    attn_mma<<<NB * (LQ / 32), 256, ATTN_SMEM>>>(attnw);
    // attended = ctx @ out_w^T + out_b + text
    gemm_mma<0><<<dim3(DIM / 128, MQ / 128), 256, GSM_TOTAL>>>(
        Chi, tOhi, tOlo, outb, text, attp, nullptr, nullptr, nullptr, nullptr, MQ, DIM, DIM);
    // layernorm
    ln_kernel<<<MQ, 256>>>(attp, lng, lnb, out);
}

// round 7
// speedup vs baseline: 4.0515x; 1.3109x over previous
#include <cuda_runtime.h>
#include <cuda_fp16.h>
#include <cstdint>
#include <cstddef>

#define DIM 1024
#define NH 16
#define HD 64
#define NB 8
#define LQ 512
#define LKK 1024
#define MQ (NB*LQ)      // 4096
#define MK (NB*LKK)     // 8192
#define EPSV 1e-5f
#define QSCALE 0.125f
#define WUP 32.0f
#define WINV (1.0f/32.0f)

// ------------------------- scratch -------------------------
__device__ float g_att[(size_t)MQ * DIM];

__device__ __half g_tAhi[(size_t)MQ * DIM];          // text fp16
__device__ __half g_tVhi[(size_t)MK * DIM];          // vision fp16
__device__ __half g_tWhi[(size_t)3*DIM*DIM];         // 32*in_proj_w fp16
__device__ __half g_tOhi[(size_t)DIM*DIM];           // 32*out_w fp16
__device__ __half g_Qhi[(size_t)MQ * DIM];           // scaled Q
__device__ __half g_Khi[(size_t)MK * DIM];
__device__ __half g_Vhi[(size_t)MK * DIM];
__device__ __half g_Chi[(size_t)MQ * DIM];           // ctx

// ------------------------- helpers -------------------------
__device__ __forceinline__ uint32_t smem_to_u32(const void* p) {
    uint32_t a;
    asm("{ .reg .u64 t; cvta.to.shared.u64 t, %1; cvt.u32.u64 %0, t; }" : "=r"(a) : "l"(p));
    return a;
}
__device__ __forceinline__ void ldsm_x4(uint32_t* r, uint32_t addr) {
    asm volatile("ldmatrix.sync.aligned.m8n8.x4.shared.b16 {%0,%1,%2,%3}, [%4];"
        : "=r"(r[0]), "=r"(r[1]), "=r"(r[2]), "=r"(r[3]) : "r"(addr));
}
__device__ __forceinline__ void ldsm_x4_t(uint32_t* r, uint32_t addr) {
    asm volatile("ldmatrix.sync.aligned.m8n8.x4.trans.shared.b16 {%0,%1,%2,%3}, [%4];"
        : "=r"(r[0]), "=r"(r[1]), "=r"(r[2]), "=r"(r[3]) : "r"(addr));
}
__device__ __forceinline__ void mma16816(float* d, const uint32_t* a, const uint32_t* b) {
    asm volatile("mma.sync.aligned.m16n8k16.row.col.f32.f16.f16.f32 "
        "{%0,%1,%2,%3}, {%4,%5,%6,%7}, {%8,%9}, {%0,%1,%2,%3};"
        : "+f"(d[0]), "+f"(d[1]), "+f"(d[2]), "+f"(d[3])
        : "r"(a[0]), "r"(a[1]), "r"(a[2]), "r"(a[3]), "r"(b[0]), "r"(b[1]));
}
__device__ __forceinline__ uint32_t h2bits(float a, float b) {
    __half2 h = __floats2half2_rn(a, b);
    return *(uint32_t*)&h;
}
__device__ __forceinline__ void cp16(uint32_t saddr, const void* g) {
    asm volatile("cp.async.cg.shared.global [%0], [%1], 16;" :: "r"(saddr), "l"(g));
}
#define CP_COMMIT() asm volatile("cp.async.commit_group;" ::: "memory")
#define CP_WAIT0()  asm volatile("cp.async.wait_group 0;" ::: "memory")

// ------------------------- conversion -------------------------
__global__ __launch_bounds__(256) void cvt_hi(const float4* __restrict__ x,
                                              uint32_t* __restrict__ hi,
                                              float scale, int n4)
{
    int i = blockIdx.x * blockDim.x + threadIdx.x;
    if (i >= n4) return;
    float4 v = x[i];
    hi[2 * i]     = h2bits(v.x * scale, v.y * scale);
    hi[2 * i + 1] = h2bits(v.z * scale, v.w * scale);
}

// ------------------------- mma.sync fp16 GEMM -------------------------
// C = A @ W^T (+bias/res). A fp16; W stored as 32*W fp16; acc * 1/32 in epilogue.
// KC=32; 2 tiles x 2 buffers = 32 KB.
#define GT_TILE 8192
#define GSM_TOTAL (4 * GT_TILE)

template<int MODE>
__global__ __launch_bounds__(256) void gemm_mma(
    const __half* __restrict__ Ahi, const __half* __restrict__ Whi,
    const float* __restrict__ bias, const float* __restrict__ res,
    float* __restrict__ C,
    __half* __restrict__ h0, __half* __restrict__ h1,
    int M, int N, int K)
{
    extern __shared__ char sm[];
    const uint32_t sb = smem_to_u32(sm);

    const int tid  = threadIdx.x;
    const int wid  = tid >> 5;
    const int lane = tid & 31;
    const int bm = blockIdx.y * 128;
    const int bn = blockIdx.x * 128;
    const int m0 = (wid >> 2) * 64;
    const int n0 = (wid & 3) * 32;

    int lrow[2], lsl[2], loff[2];
#pragma unroll
    for (int i = 0; i < 2; i++) {
        int u = tid + i * 256;
        lrow[i] = u >> 2;
        lsl[i]  = u & 3;
        loff[i] = lrow[i] * 64 + ((lsl[i] << 4) ^ (((lrow[i] >> 1) & 3) << 4));
    }

    const int arow_l = lane & 15;
    const int a_hi   = lane >> 4;
    const int brow_l = (lane & 7) + ((lane & 16) ? 8 : 0);
    const int b_hi   = (lane & 8) ? 1 : 0;
    const int gid = lane >> 2, tig = lane & 3;

    float acc[4][4][4];
#pragma unroll
    for (int i = 0; i < 4; i++)
#pragma unroll
        for (int j = 0; j < 4; j++)
#pragma unroll
            for (int l = 0; l < 4; l++) acc[i][j][l] = 0.f;

    const int nch = K >> 5;

    {
#pragma unroll
        for (int i = 0; i < 2; i++) {
            const int col = lsl[i] * 8;
            cp16(sb + loff[i],           Ahi + (size_t)(bm + lrow[i]) * K + col);
            cp16(sb + GT_TILE + loff[i], Whi + (size_t)(bn + lrow[i]) * K + col);
        }
        CP_COMMIT();
    }

    for (int c = 0; c < nch; c++) {
        CP_WAIT0();
        __syncthreads();
        if (c + 1 < nch) {
            const uint32_t base = sb + ((c + 1) & 1) * 2 * GT_TILE;
            const int coff = (c + 1) * 32;
#pragma unroll
            for (int i = 0; i < 2; i++) {
                const int col = coff + lsl[i] * 8;
                cp16(base + loff[i],           Ahi + (size_t)(bm + lrow[i]) * K + col);
                cp16(base + GT_TILE + loff[i], Whi + (size_t)(bn + lrow[i]) * K + col);
            }
            CP_COMMIT();
        }
        const uint32_t tb = sb + (c & 1) * 2 * GT_TILE;
#pragma unroll
        for (int ks = 0; ks < 2; ks++) {
            uint32_t ah[4][4];
#pragma unroll
            for (int mf = 0; mf < 4; mf++) {
                const int row = m0 + mf * 16 + arow_l;
                const int sl  = ks * 2 + a_hi;
                ldsm_x4(ah[mf], tb + row * 64 + ((sl << 4) ^ (((row >> 1) & 3) << 4)));
            }
            uint32_t bh[2][4];
#pragma unroll
            for (int np = 0; np < 2; np++) {
                const int row = n0 + np * 16 + brow_l;
                const int sl  = ks * 2 + b_hi;
                ldsm_x4(bh[np], tb + GT_TILE + row * 64 + ((sl << 4) ^ (((row >> 1) & 3) << 4)));
            }
#pragma unroll
            for (int mf = 0; mf < 4; mf++)
#pragma unroll
                for (int np = 0; np < 2; np++)
#pragma unroll
                    for (int half = 0; half < 2; half++)
                        mma16816(acc[mf][np * 2 + half], ah[mf], &bh[np][half * 2]);
        }
    }

    // ---- epilogue ----
#pragma unroll
    for (int mf = 0; mf < 4; mf++) {
        const int mrow0 = bm + m0 + mf * 16 + gid;
#pragma unroll
        for (int nf = 0; nf < 4; nf++) {
            const int col = bn + n0 + nf * 8 + tig * 2;
            const float2 bia = *(const float2*)&bias[col];
            float* d = acc[mf][nf];
            float v00 = d[0] * WINV + bia.x, v01 = d[1] * WINV + bia.y;
            float v10 = d[2] * WINV + bia.x, v11 = d[3] * WINV + bia.y;
            if (MODE == 0) {
                const size_t i0 = (size_t)mrow0 * N + col;
                const size_t i1 = (size_t)(mrow0 + 8) * N + col;
                if (res) {
                    float2 r0 = *(const float2*)&res[i0];
                    float2 r1 = *(const float2*)&res[i1];
                    v00 += r0.x; v01 += r0.y; v10 += r1.x; v11 += r1.y;
                }
                *(float2*)&C[i0] = make_float2(v00, v01);
                *(float2*)&C[i1] = make_float2(v10, v11);
            } else if (MODE == 1) {
                v00 *= QSCALE; v01 *= QSCALE; v10 *= QSCALE; v11 *= QSCALE;
                const size_t i0 = (size_t)mrow0 * DIM + col;
                const size_t i1 = (size_t)(mrow0 + 8) * DIM + col;
                *(uint32_t*)&h0[i0] = h2bits(v00, v01);
                *(uint32_t*)&h0[i1] = h2bits(v10, v11);
            } else {
                __half* H = h0;
                int cc = col;
                if (col >= DIM) { H = h1; cc = col - DIM; }
                const size_t i0 = (size_t)mrow0 * DIM + cc;
                const size_t i1 = (size_t)(mrow0 + 8) * DIM + cc;
                *(uint32_t*)&H[i0] = h2bits(v00, v01);
                *(uint32_t*)&H[i1] = h2bits(v10, v11);
            }
        }
    }
}

// ------------------------- tensor-core attention (fp16 single-pass) -------------------------
#define SM_QH  131072
#define SM_KV0 135168
#define KV_BUF 16384
#define ATTN_SMEM (SM_KV0 + 2 * KV_BUF)   // 167936

__global__ __launch_bounds__(256) void attn_mma(float* __restrict__ attnw)
{
    extern __shared__ char sm[];
    float* S = (float*)sm;
    const uint32_t sb = smem_to_u32(sm);

    const int tid  = threadIdx.x;
    const int wid  = tid >> 5;
    const int lane = tid & 31;
    const int b  = blockIdx.x >> 4;
    const int q0 = (blockIdx.x & 15) << 5;

    const int ms  = (wid >> 2) * 16;
    const int ns  = (wid & 3) * 32;
    const int nv0 = (wid & 3) * 16;

    const int arow_l = lane & 15;
    const int axor   = (arow_l & 7) << 4;
    const int akb    = (lane >> 4) * 16;
    const int brow_l = (lane & 7) + ((lane & 16) ? 8 : 0);
    const int bxor   = (lane & 7) << 4;
    const int bkb    = (lane & 8) ? 16 : 0;
    const int gid = lane >> 2, tig = lane & 3;

    int krow[4], koff_s[4], kcu[4];
#pragma unroll
    for (int i = 0; i < 4; i++) {
        int u = tid + i * 256;
        krow[i] = u >> 3;
        kcu[i]  = u & 7;
        koff_s[i] = krow[i] * 128 + ((kcu[i] * 16) ^ ((krow[i] & 7) << 4));
    }
    const int qrow = tid >> 3, qcu = tid & 7;
    const int qoff = qrow * 128 + ((qcu * 16) ^ ((qrow & 7) << 4));

    const int vkey_l = ((lane >> 3) & 1) * 8 + (lane & 7);
    const int vdim   = nv0 + ((lane >> 4) ? 8 : 0);

    for (int h = 0; h < NH; h++) {
        {
            size_t g = ((size_t)(b * LQ + q0 + qrow)) * DIM + h * HD + qcu * 8;
            *(uint4*)(sm + SM_QH + qoff) = *(const uint4*)(g_Qhi + g);
        }
        __syncthreads();

        // K chunk 0 -> buf 0
        {
#pragma unroll
            for (int i = 0; i < 4; i++) {
                size_t g = ((size_t)(b * LKK + krow[i])) * DIM + h * HD + kcu[i] * 8;
                cp16(sb + SM_KV0 + koff_s[i], g_Khi + g);
            }
            CP_COMMIT();
        }

        uint32_t qh[4][4];
#pragma unroll
        for (int ks = 0; ks < 4; ks++) {
            int koff = (ks * 32 + akb) ^ axor;
            ldsm_x4(qh[ks], sb + SM_QH + (ms + arow_l) * 128 + koff);
        }

        // ---- scores ----
        for (int kc = 0; kc < 8; kc++) {
            CP_WAIT0();
            __syncthreads();
            if (kc < 7) {
                const uint32_t base = sb + SM_KV0 + ((kc + 1) & 1) * KV_BUF;
#pragma unroll
                for (int i = 0; i < 4; i++) {
                    size_t g = ((size_t)(b * LKK + (kc + 1) * 128 + krow[i])) * DIM + h * HD + kcu[i] * 8;
                    cp16(base + koff_s[i], g_Khi + g);
                }
                CP_COMMIT();
            }
            const uint32_t kb = sb + SM_KV0 + (kc & 1) * KV_BUF;
            float acc[4][4];
#pragma unroll
            for (int i = 0; i < 4; i++)
#pragma unroll
                for (int j = 0; j < 4; j++) acc[i][j] = 0.f;
#pragma unroll
            for (int ks = 0; ks < 4; ks++) {
                const int bkoff = (ks * 32 + bkb) ^ bxor;
                uint32_t bh[2][4];
#pragma unroll
                for (int np = 0; np < 2; np++)
                    ldsm_x4(bh[np], kb + (ns + np * 16 + brow_l) * 128 + bkoff);
#pragma unroll
                for (int np = 0; np < 2; np++)
#pragma unroll
                    for (int half = 0; half < 2; half++)
                        mma16816(acc[np * 2 + half], qh[ks], &bh[np][half * 2]);
            }
#pragma unroll
            for (int nf = 0; nf < 4; nf++) {
                const int col = kc * 128 + ns + nf * 8 + tig * 2;
                *(float2*)&S[(ms + gid) * LKK + col]     = make_float2(acc[nf][0], acc[nf][1]);
                *(float2*)&S[(ms + gid + 8) * LKK + col] = make_float2(acc[nf][2], acc[nf][3]);
            }
        }
        __syncthreads();

        // V chunk 0 -> buf 0 (overlaps softmax)
        {
#pragma unroll
            for (int i = 0; i < 4; i++) {
                size_t g = ((size_t)(b * LKK + krow[i])) * DIM + h * HD + kcu[i] * 8;
                cp16(sb + SM_KV0 + koff_s[i], g_Vhi + g);
            }
            CP_COMMIT();
        }

        // ---- fused softmax + attnw + fp16 convert ----
        {
            const float invh = 1.0f / NH;
            for (int r = wid * 4; r < wid * 4 + 4; r++) {
                float v[32];
                const float* src = &S[r * LKK + lane * 32];
#pragma unroll
                for (int j = 0; j < 8; j++) *(float4*)&v[j * 4] = *(const float4*)&src[j * 4];
                float mx = -1e30f;
#pragma unroll
                for (int j = 0; j < 32; j++) mx = fmaxf(mx, v[j]);
#pragma unroll
                for (int o = 16; o > 0; o >>= 1) mx = fmaxf(mx, __shfl_xor_sync(0xffffffffu, mx, o));
                float s = 0.f;
#pragma unroll
                for (int j = 0; j < 32; j++) { v[j] = __expf(v[j] - mx); s += v[j]; }
#pragma unroll
                for (int o = 16; o > 0; o >>= 1) s += __shfl_xor_sync(0xffffffffu, s, o);
                const float inv = 1.0f / s;
#pragma unroll
                for (int j = 0; j < 32; j++) v[j] *= inv;

                float* aw = attnw + ((size_t)(b * LQ + q0 + r)) * LKK + lane * 32;
                if (h == 0) {
#pragma unroll
                    for (int j = 0; j < 8; j++) {
                        float4 p = make_float4(v[j*4]*invh, v[j*4+1]*invh, v[j*4+2]*invh, v[j*4+3]*invh);
                        *(float4*)&aw[j * 4] = p;
                    }
                } else {
#pragma unroll
                    for (int j = 0; j < 8; j++) {
                        float4 o4 = *(const float4*)&aw[j * 4];
                        o4.x += v[j*4]*invh; o4.y += v[j*4+1]*invh;
                        o4.z += v[j*4+2]*invh; o4.w += v[j*4+3]*invh;
                        *(float4*)&aw[j * 4] = o4;
                    }
                }
                char* rb = sm + r * 4096;
                const int sw = (r & 7) << 4;
#pragma unroll
                for (int j = 0; j < 4; j++) {
                    uint32_t h4[4];
#pragma unroll
                    for (int p = 0; p < 4; p++)
                        h4[p] = h2bits(v[j * 8 + p * 2], v[j * 8 + p * 2 + 1]);
                    const int off = ((lane * 4 + j) * 16) ^ sw;
                    *(uint4*)(rb + off) = *(uint4*)h4;
                }
            }
        }

        // ---- ctx = P @ V ----
        float cacc[2][4];
#pragma unroll
        for (int g = 0; g < 2; g++)
#pragma unroll
            for (int l = 0; l < 4; l++) cacc[g][l] = 0.f;

        for (int kc = 0; kc < 8; kc++) {
            CP_WAIT0();
            __syncthreads();
            if (kc < 7) {
                const uint32_t base = sb + SM_KV0 + ((kc + 1) & 1) * KV_BUF;
#pragma unroll
                for (int i = 0; i < 4; i++) {
                    size_t g = ((size_t)(b * LKK + (kc + 1) * 128 + krow[i])) * DIM + h * HD + kcu[i] * 8;
                    cp16(base + koff_s[i], g_Vhi + g);
                }
                CP_COMMIT();
            }
            const uint32_t vb = sb + SM_KV0 + (kc & 1) * KV_BUF;
            const int mrow = ms + arow_l;
            const uint32_t pbase = sb + mrow * 4096;
            const int psw = (mrow & 7) << 4;
#pragma unroll
            for (int ks = 0; ks < 8; ks++) {
                const int poff = ((kc * 256 + ks * 32 + akb) ^ psw);
                uint32_t pah[4];
                ldsm_x4(pah, pbase + poff);
                const int key = ks * 16 + vkey_l;
                const uint32_t vaddr = vb + key * 128 + ((vdim * 2) ^ ((key & 7) << 4));
                uint32_t vh[4];
                ldsm_x4_t(vh, vaddr);
#pragma unroll
                for (int g = 0; g < 2; g++)
                    mma16816(cacc[g], pah, &vh[g * 2]);
            }
        }
#pragma unroll
        for (int g = 0; g < 2; g++) {
            const int col = h * HD + nv0 + g * 8 + tig * 2;
            const size_t i0 = ((size_t)(b * LQ + q0 + ms + gid)) * DIM + col;
            const size_t i1 = ((size_t)(b * LQ + q0 + ms + gid + 8)) * DIM + col;
            *(uint32_t*)&g_Chi[i0] = h2bits(cacc[g][0], cacc[g][1]);
            *(uint32_t*)&g_Chi[i1] = h2bits(cacc[g][2], cacc[g][3]);
        }
    }
}

// ------------------------- layernorm -------------------------
__global__ __launch_bounds__(256) void ln_kernel(
    const float* __restrict__ X, const float* __restrict__ gam,
    const float* __restrict__ bet, float* __restrict__ out)
{
    __shared__ float red[64];
    __shared__ float s_mu, s_rinv;
    const int r = blockIdx.x, tid = threadIdx.x;
    const float* x = X + (size_t)r * DIM;
    float4 v = *(const float4*)&x[tid * 4];
    float s  = v.x + v.y + v.z + v.w;
    float sq = v.x * v.x + v.y * v.y + v.z * v.z + v.w * v.w;
#pragma unroll
    for (int o = 16; o > 0; o >>= 1) {
        s  += __shfl_xor_sync(0xffffffffu, s, o);
        sq += __shfl_xor_sync(0xffffffffu, sq, o);
    }
    const int w = tid >> 5;
    if ((tid & 31) == 0) { red[w] = s; red[32 + w] = sq; }
    __syncthreads();
    if (tid == 0) {
        float S = 0, Q = 0;
        for (int i = 0; i < 8; i++) { S += red[i]; Q += red[32 + i]; }
        float mu = S * (1.0f / DIM);
        float var = Q * (1.0f / DIM) - mu * mu;
        s_mu = mu;
        s_rinv = rsqrtf(var + EPSV);
    }
    __syncthreads();
    const float mu = s_mu, rinv = s_rinv;
    float4 gg = *(const float4*)&gam[tid * 4];
    float4 bb = *(const float4*)&bet[tid * 4];
    float4 o;
    o.x = (v.x - mu) * rinv * gg.x + bb.x;
    o.y = (v.y - mu) * rinv * gg.y + bb.y;
    o.z = (v.z - mu) * rinv * gg.z + bb.z;
    o.w = (v.w - mu) * rinv * gg.w + bb.w;
    *(float4*)&out[(size_t)r * DIM + tid * 4] = o;
}

// ------------------------- launch -------------------------
extern "C" void kernel_launch(void* const* d_in, const int* in_sizes, int n_in,
                              void* d_out, int out_size)
{
    const float* text   = (const float*)d_in[0];
    const float* vision = (const float*)d_in[1];
    const float* ipw    = (const float*)d_in[2];
    const float* ipb    = (const float*)d_in[3];
    const float* outw   = (const float*)d_in[4];
    const float* outb   = (const float*)d_in[5];
    const float* lng    = (const float*)d_in[6];
    const float* lnb    = (const float*)d_in[7];

    float* out   = (float*)d_out;
    float* attnw = out + (size_t)MQ * DIM;

    float* attp;
    cudaGetSymbolAddress((void**)&attp, g_att);

    __half *tAhi, *tVhi, *tWhi, *tOhi, *Qhi, *Khi, *Vhi, *Chi;
    cudaGetSymbolAddress((void**)&tAhi, g_tAhi);
    cudaGetSymbolAddress((void**)&tVhi, g_tVhi);
    cudaGetSymbolAddress((void**)&tWhi, g_tWhi);
    cudaGetSymbolAddress((void**)&tOhi, g_tOhi);
    cudaGetSymbolAddress((void**)&Qhi, g_Qhi);
    cudaGetSymbolAddress((void**)&Khi, g_Khi);
    cudaGetSymbolAddress((void**)&Vhi, g_Vhi);
    cudaGetSymbolAddress((void**)&Chi, g_Chi);

    cudaFuncSetAttribute(attn_mma, cudaFuncAttributeMaxDynamicSharedMemorySize, ATTN_SMEM);
    cudaFuncSetAttribute(gemm_mma<0>, cudaFuncAttributeMaxDynamicSharedMemorySize, GSM_TOTAL);
    cudaFuncSetAttribute(gemm_mma<1>, cudaFuncAttributeMaxDynamicSharedMemorySize, GSM_TOTAL);
    cudaFuncSetAttribute(gemm_mma<2>, cudaFuncAttributeMaxDynamicSharedMemorySize, GSM_TOTAL);

    int n4;
    n4 = (MQ * DIM) / 4;
    cvt_hi<<<(n4 + 255) / 256, 256>>>((const float4*)text, (uint32_t*)tAhi, 1.0f, n4);
    n4 = (MK * DIM) / 4;
    cvt_hi<<<(n4 + 255) / 256, 256>>>((const float4*)vision, (uint32_t*)tVhi, 1.0f, n4);
    n4 = (3 * DIM * DIM) / 4;
    cvt_hi<<<(n4 + 255) / 256, 256>>>((const float4*)ipw, (uint32_t*)tWhi, WUP, n4);
    n4 = (DIM * DIM) / 4;
    cvt_hi<<<(n4 + 255) / 256, 256>>>((const float4*)outw, (uint32_t*)tOhi, WUP, n4);

    // Q (scaled fp16) = 0.125*(text @ Wq^T + bq)
    gemm_mma<1><<<dim3(DIM / 128, MQ / 128), 256, GSM_TOTAL>>>(
        tAhi, tWhi, ipb, nullptr, nullptr, Qhi, nullptr, MQ, DIM, DIM);
    // [K|V] fp16 = vision @ [Wk|Wv]^T + [bk|bv]
    gemm_mma<2><<<dim3(2 * DIM / 128, MK / 128), 256, GSM_TOTAL>>>(
        tVhi, tWhi + (size_t)DIM * DIM, ipb + DIM, nullptr, nullptr, Khi, Vhi, MK, 2 * DIM, DIM);
    // attention
    attn_mma<<<NB * (LQ / 32), 256, ATTN_SMEM>>>(attnw);
    // attended = ctx @ out_w^T + out_b + text
    gemm_mma<0><<<dim3(DIM / 128, MQ / 128), 256, GSM_TOTAL>>>(
        Chi, tOhi, outb, text, attp, nullptr, nullptr, MQ, DIM, DIM);
    // layernorm
    ln_kernel<<<MQ, 256>>>(attp, lng, lnb, out);
}

// round 8
// speedup vs baseline: 5.5171x; 1.3617x over previous
#include <cuda_runtime.h>
#include <cuda_fp16.h>
#include <cstdint>
#include <cstddef>

#define DIM 1024
#define NH 16
#define HD 64
#define NB 8
#define LQ 512
#define LKK 1024
#define MQ (NB*LQ)      // 4096
#define MK (NB*LKK)     // 8192
#define EPSV 1e-5f
#define QSCALE 0.125f
#define WUP 32.0f
#define WINV (1.0f/32.0f)

// ------------------------- scratch -------------------------
__device__ float g_att[(size_t)MQ * DIM];

__device__ __half g_tAhi[(size_t)MQ * DIM];          // text fp16
__device__ __half g_tVhi[(size_t)MK * DIM];          // vision fp16
__device__ __half g_tWhi[(size_t)3*DIM*DIM];         // 32*in_proj_w fp16
__device__ __half g_tOhi[(size_t)DIM*DIM];           // 32*out_w fp16
__device__ __half g_Qhi[(size_t)MQ * DIM];           // scaled Q
__device__ __half g_Khi[(size_t)MK * DIM];
__device__ __half g_Vhi[(size_t)MK * DIM];
__device__ __half g_Chi[(size_t)MQ * DIM];           // ctx

// ------------------------- helpers -------------------------
__device__ __forceinline__ uint32_t smem_to_u32(const void* p) {
    uint32_t a;
    asm("{ .reg .u64 t; cvta.to.shared.u64 t, %1; cvt.u32.u64 %0, t; }" : "=r"(a) : "l"(p));
    return a;
}
__device__ __forceinline__ void ldsm_x4(uint32_t* r, uint32_t addr) {
    asm volatile("ldmatrix.sync.aligned.m8n8.x4.shared.b16 {%0,%1,%2,%3}, [%4];"
        : "=r"(r[0]), "=r"(r[1]), "=r"(r[2]), "=r"(r[3]) : "r"(addr));
}
__device__ __forceinline__ void ldsm_x4_t(uint32_t* r, uint32_t addr) {
    asm volatile("ldmatrix.sync.aligned.m8n8.x4.trans.shared.b16 {%0,%1,%2,%3}, [%4];"
        : "=r"(r[0]), "=r"(r[1]), "=r"(r[2]), "=r"(r[3]) : "r"(addr));
}
__device__ __forceinline__ void mma16816(float* d, const uint32_t* a, const uint32_t* b) {
    asm volatile("mma.sync.aligned.m16n8k16.row.col.f32.f16.f16.f32 "
        "{%0,%1,%2,%3}, {%4,%5,%6,%7}, {%8,%9}, {%0,%1,%2,%3};"
        : "+f"(d[0]), "+f"(d[1]), "+f"(d[2]), "+f"(d[3])
        : "r"(a[0]), "r"(a[1]), "r"(a[2]), "r"(a[3]), "r"(b[0]), "r"(b[1]));
}
__device__ __forceinline__ uint32_t h2bits(float a, float b) {
    __half2 h = __floats2half2_rn(a, b);
    return *(uint32_t*)&h;
}
__device__ __forceinline__ void cp16(uint32_t saddr, const void* g) {
    asm volatile("cp.async.cg.shared.global [%0], [%1], 16;" :: "r"(saddr), "l"(g));
}
#define CP_COMMIT() asm volatile("cp.async.commit_group;" ::: "memory")
#define CP_WAIT0()  asm volatile("cp.async.wait_group 0;" ::: "memory")

// ------------------------- conversion -------------------------
__global__ __launch_bounds__(256) void cvt_hi(const float4* __restrict__ x,
                                              uint32_t* __restrict__ hi,
                                              float scale, int n4)
{
    int i = blockIdx.x * blockDim.x + threadIdx.x;
    if (i >= n4) return;
    float4 v = x[i];
    hi[2 * i]     = h2bits(v.x * scale, v.y * scale);
    hi[2 * i + 1] = h2bits(v.z * scale, v.w * scale);
}

// ------------------------- mma.sync fp16 GEMM -------------------------
#define GT_TILE 8192
#define GSM_TOTAL (4 * GT_TILE)

template<int MODE>
__global__ __launch_bounds__(256) void gemm_mma(
    const __half* __restrict__ Ahi, const __half* __restrict__ Whi,
    const float* __restrict__ bias, const float* __restrict__ res,
    float* __restrict__ C,
    __half* __restrict__ h0, __half* __restrict__ h1,
    int M, int N, int K)
{
    extern __shared__ char sm[];
    const uint32_t sb = smem_to_u32(sm);

    const int tid  = threadIdx.x;
    const int wid  = tid >> 5;
    const int lane = tid & 31;
    const int bm = blockIdx.y * 128;
    const int bn = blockIdx.x * 128;
    const int m0 = (wid >> 2) * 64;
    const int n0 = (wid & 3) * 32;

    int lrow[2], lsl[2], loff[2];
#pragma unroll
    for (int i = 0; i < 2; i++) {
        int u = tid + i * 256;
        lrow[i] = u >> 2;
        lsl[i]  = u & 3;
        loff[i] = lrow[i] * 64 + ((lsl[i] << 4) ^ (((lrow[i] >> 1) & 3) << 4));
    }

    const int arow_l = lane & 15;
    const int a_hi   = lane >> 4;
    const int brow_l = (lane & 7) + ((lane & 16) ? 8 : 0);
    const int b_hi   = (lane & 8) ? 1 : 0;
    const int gid = lane >> 2, tig = lane & 3;

    float acc[4][4][4];
#pragma unroll
    for (int i = 0; i < 4; i++)
#pragma unroll
        for (int j = 0; j < 4; j++)
#pragma unroll
            for (int l = 0; l < 4; l++) acc[i][j][l] = 0.f;

    const int nch = K >> 5;

    {
#pragma unroll
        for (int i = 0; i < 2; i++) {
            const int col = lsl[i] * 8;
            cp16(sb + loff[i],           Ahi + (size_t)(bm + lrow[i]) * K + col);
            cp16(sb + GT_TILE + loff[i], Whi + (size_t)(bn + lrow[i]) * K + col);
        }
        CP_COMMIT();
    }

    for (int c = 0; c < nch; c++) {
        CP_WAIT0();
        __syncthreads();
        if (c + 1 < nch) {
            const uint32_t base = sb + ((c + 1) & 1) * 2 * GT_TILE;
            const int coff = (c + 1) * 32;
#pragma unroll
            for (int i = 0; i < 2; i++) {
                const int col = coff + lsl[i] * 8;
                cp16(base + loff[i],           Ahi + (size_t)(bm + lrow[i]) * K + col);
                cp16(base + GT_TILE + loff[i], Whi + (size_t)(bn + lrow[i]) * K + col);
            }
            CP_COMMIT();
        }
        const uint32_t tb = sb + (c & 1) * 2 * GT_TILE;
#pragma unroll
        for (int ks = 0; ks < 2; ks++) {
            uint32_t ah[4][4];
#pragma unroll
            for (int mf = 0; mf < 4; mf++) {
                const int row = m0 + mf * 16 + arow_l;
                const int sl  = ks * 2 + a_hi;
                ldsm_x4(ah[mf], tb + row * 64 + ((sl << 4) ^ (((row >> 1) & 3) << 4)));
            }
            uint32_t bh[2][4];
#pragma unroll
            for (int np = 0; np < 2; np++) {
                const int row = n0 + np * 16 + brow_l;
                const int sl  = ks * 2 + b_hi;
                ldsm_x4(bh[np], tb + GT_TILE + row * 64 + ((sl << 4) ^ (((row >> 1) & 3) << 4)));
            }
#pragma unroll
            for (int mf = 0; mf < 4; mf++)
#pragma unroll
                for (int np = 0; np < 2; np++)
#pragma unroll
                    for (int half = 0; half < 2; half++)
                        mma16816(acc[mf][np * 2 + half], ah[mf], &bh[np][half * 2]);
        }
    }

    // ---- epilogue ----
#pragma unroll
    for (int mf = 0; mf < 4; mf++) {
        const int mrow0 = bm + m0 + mf * 16 + gid;
#pragma unroll
        for (int nf = 0; nf < 4; nf++) {
            const int col = bn + n0 + nf * 8 + tig * 2;
            const float2 bia = *(const float2*)&bias[col];
            float* d = acc[mf][nf];
            float v00 = d[0] * WINV + bia.x, v01 = d[1] * WINV + bia.y;
            float v10 = d[2] * WINV + bia.x, v11 = d[3] * WINV + bia.y;
            if (MODE == 0) {
                const size_t i0 = (size_t)mrow0 * N + col;
                const size_t i1 = (size_t)(mrow0 + 8) * N + col;
                if (res) {
                    float2 r0 = *(const float2*)&res[i0];
                    float2 r1 = *(const float2*)&res[i1];
                    v00 += r0.x; v01 += r0.y; v10 += r1.x; v11 += r1.y;
                }
                *(float2*)&C[i0] = make_float2(v00, v01);
                *(float2*)&C[i1] = make_float2(v10, v11);
            } else if (MODE == 1) {
                v00 *= QSCALE; v01 *= QSCALE; v10 *= QSCALE; v11 *= QSCALE;
                const size_t i0 = (size_t)mrow0 * DIM + col;
                const size_t i1 = (size_t)(mrow0 + 8) * DIM + col;
                *(uint32_t*)&h0[i0] = h2bits(v00, v01);
                *(uint32_t*)&h0[i1] = h2bits(v10, v11);
            } else {
                __half* H = h0;
                int cc = col;
                if (col >= DIM) { H = h1; cc = col - DIM; }
                const size_t i0 = (size_t)mrow0 * DIM + cc;
                const size_t i1 = (size_t)(mrow0 + 8) * DIM + cc;
                *(uint32_t*)&H[i0] = h2bits(v00, v01);
                *(uint32_t*)&H[i1] = h2bits(v10, v11);
            }
        }
    }
}

// ------------------------- tensor-core attention -------------------------
// attn_weights accumulated in registers across all 16 heads, written once.
#define SM_QH  131072
#define SM_KV0 135168
#define KV_BUF 16384
#define ATTN_SMEM (SM_KV0 + 2 * KV_BUF)   // 167936

__global__ __launch_bounds__(256) void attn_mma(float* __restrict__ attnw)
{
    extern __shared__ char sm[];
    float* S = (float*)sm;
    const uint32_t sb = smem_to_u32(sm);

    const int tid  = threadIdx.x;
    const int wid  = tid >> 5;
    const int lane = tid & 31;
    const int b  = blockIdx.x >> 4;
    const int q0 = (blockIdx.x & 15) << 5;

    const int ms  = (wid >> 2) * 16;
    const int ns  = (wid & 3) * 32;
    const int nv0 = (wid & 3) * 16;

    const int arow_l = lane & 15;
    const int axor   = (arow_l & 7) << 4;
    const int akb    = (lane >> 4) * 16;
    const int brow_l = (lane & 7) + ((lane & 16) ? 8 : 0);
    const int bxor   = (lane & 7) << 4;
    const int bkb    = (lane & 8) ? 16 : 0;
    const int gid = lane >> 2, tig = lane & 3;

    int krow[4], koff_s[4], kcu[4];
#pragma unroll
    for (int i = 0; i < 4; i++) {
        int u = tid + i * 256;
        krow[i] = u >> 3;
        kcu[i]  = u & 7;
        koff_s[i] = krow[i] * 128 + ((kcu[i] * 16) ^ ((krow[i] & 7) << 4));
    }
    const int qrow = tid >> 3, qcu = tid & 7;
    const int qoff = qrow * 128 + ((qcu * 16) ^ ((qrow & 7) << 4));

    const int vkey_l = ((lane >> 3) & 1) * 8 + (lane & 7);
    const int vdim   = nv0 + ((lane >> 4) ? 8 : 0);

    // attn_weights accumulator: rows wid*4+rr, cols lane*32+j
    float awacc[4][32];
#pragma unroll
    for (int rr = 0; rr < 4; rr++)
#pragma unroll
        for (int j = 0; j < 32; j++) awacc[rr][j] = 0.f;

    for (int h = 0; h < NH; h++) {
        {
            size_t g = ((size_t)(b * LQ + q0 + qrow)) * DIM + h * HD + qcu * 8;
            *(uint4*)(sm + SM_QH + qoff) = *(const uint4*)(g_Qhi + g);
        }
        __syncthreads();

        // K chunk 0 -> buf 0
        {
#pragma unroll
            for (int i = 0; i < 4; i++) {
                size_t g = ((size_t)(b * LKK + krow[i])) * DIM + h * HD + kcu[i] * 8;
                cp16(sb + SM_KV0 + koff_s[i], g_Khi + g);
            }
            CP_COMMIT();
        }

        uint32_t qh[4][4];
#pragma unroll
        for (int ks = 0; ks < 4; ks++) {
            int koff = (ks * 32 + akb) ^ axor;
            ldsm_x4(qh[ks], sb + SM_QH + (ms + arow_l) * 128 + koff);
        }

        // ---- scores ----
        for (int kc = 0; kc < 8; kc++) {
            CP_WAIT0();
            __syncthreads();
            if (kc < 7) {
                const uint32_t base = sb + SM_KV0 + ((kc + 1) & 1) * KV_BUF;
#pragma unroll
                for (int i = 0; i < 4; i++) {
                    size_t g = ((size_t)(b * LKK + (kc + 1) * 128 + krow[i])) * DIM + h * HD + kcu[i] * 8;
                    cp16(base + koff_s[i], g_Khi + g);
                }
                CP_COMMIT();
            }
            const uint32_t kb = sb + SM_KV0 + (kc & 1) * KV_BUF;
            float acc[4][4];
#pragma unroll
            for (int i = 0; i < 4; i++)
#pragma unroll
                for (int j = 0; j < 4; j++) acc[i][j] = 0.f;
#pragma unroll
            for (int ks = 0; ks < 4; ks++) {
                const int bkoff = (ks * 32 + bkb) ^ bxor;
                uint32_t bh[2][4];
#pragma unroll
                for (int np = 0; np < 2; np++)
                    ldsm_x4(bh[np], kb + (ns + np * 16 + brow_l) * 128 + bkoff);
#pragma unroll
                for (int np = 0; np < 2; np++)
#pragma unroll
                    for (int half = 0; half < 2; half++)
                        mma16816(acc[np * 2 + half], qh[ks], &bh[np][half * 2]);
            }
#pragma unroll
            for (int nf = 0; nf < 4; nf++) {
                const int col = kc * 128 + ns + nf * 8 + tig * 2;
                *(float2*)&S[(ms + gid) * LKK + col]     = make_float2(acc[nf][0], acc[nf][1]);
                *(float2*)&S[(ms + gid + 8) * LKK + col] = make_float2(acc[nf][2], acc[nf][3]);
            }
        }
        __syncthreads();

        // V chunk 0 -> buf 0 (overlaps softmax)
        {
#pragma unroll
            for (int i = 0; i < 4; i++) {
                size_t g = ((size_t)(b * LKK + krow[i])) * DIM + h * HD + kcu[i] * 8;
                cp16(sb + SM_KV0 + koff_s[i], g_Vhi + g);
            }
            CP_COMMIT();
        }

        // ---- fused softmax + register attnw accumulation + fp16 convert ----
#pragma unroll
        for (int rr = 0; rr < 4; rr++) {
            const int r = wid * 4 + rr;
            float v[32];
            const float* src = &S[r * LKK + lane * 32];
#pragma unroll
            for (int j = 0; j < 8; j++) *(float4*)&v[j * 4] = *(const float4*)&src[j * 4];
            float mx = -1e30f;
#pragma unroll
            for (int j = 0; j < 32; j++) mx = fmaxf(mx, v[j]);
#pragma unroll
            for (int o = 16; o > 0; o >>= 1) mx = fmaxf(mx, __shfl_xor_sync(0xffffffffu, mx, o));
            float s = 0.f;
#pragma unroll
            for (int j = 0; j < 32; j++) { v[j] = __expf(v[j] - mx); s += v[j]; }
#pragma unroll
            for (int o = 16; o > 0; o >>= 1) s += __shfl_xor_sync(0xffffffffu, s, o);
            const float inv = 1.0f / s;
#pragma unroll
            for (int j = 0; j < 32; j++) v[j] *= inv;

            // accumulate attn_weights in registers
#pragma unroll
            for (int j = 0; j < 32; j++) awacc[rr][j] += v[j];

            // P fp16: row r -> bytes [0,2048) of rb
            char* rb = sm + r * 4096;
            const int sw = (r & 7) << 4;
#pragma unroll
            for (int j = 0; j < 4; j++) {
                uint32_t h4[4];
#pragma unroll
                for (int p = 0; p < 4; p++)
                    h4[p] = h2bits(v[j * 8 + p * 2], v[j * 8 + p * 2 + 1]);
                const int off = ((lane * 4 + j) * 16) ^ sw;
                *(uint4*)(rb + off) = *(uint4*)h4;
            }
        }

        // ---- ctx = P @ V ----
        float cacc[2][4];
#pragma unroll
        for (int g = 0; g < 2; g++)
#pragma unroll
            for (int l = 0; l < 4; l++) cacc[g][l] = 0.f;

        for (int kc = 0; kc < 8; kc++) {
            CP_WAIT0();
            __syncthreads();
            if (kc < 7) {
                const uint32_t base = sb + SM_KV0 + ((kc + 1) & 1) * KV_BUF;
#pragma unroll
                for (int i = 0; i < 4; i++) {
                    size_t g = ((size_t)(b * LKK + (kc + 1) * 128 + krow[i])) * DIM + h * HD + kcu[i] * 8;
                    cp16(base + koff_s[i], g_Vhi + g);
                }
                CP_COMMIT();
            }
            const uint32_t vb = sb + SM_KV0 + (kc & 1) * KV_BUF;
            const int mrow = ms + arow_l;
            const uint32_t pbase = sb + mrow * 4096;
            const int psw = (mrow & 7) << 4;
#pragma unroll
            for (int ks = 0; ks < 8; ks++) {
                const int poff = ((kc * 256 + ks * 32 + akb) ^ psw);
                uint32_t pah[4];
                ldsm_x4(pah, pbase + poff);
                const int key = ks * 16 + vkey_l;
                const uint32_t vaddr = vb + key * 128 + ((vdim * 2) ^ ((key & 7) << 4));
                uint32_t vh[4];
                ldsm_x4_t(vh, vaddr);
#pragma unroll
                for (int g = 0; g < 2; g++)
                    mma16816(cacc[g], pah, &vh[g * 2]);
            }
        }
#pragma unroll
        for (int g = 0; g < 2; g++) {
            const int col = h * HD + nv0 + g * 8 + tig * 2;
            const size_t i0 = ((size_t)(b * LQ + q0 + ms + gid)) * DIM + col;
            const size_t i1 = ((size_t)(b * LQ + q0 + ms + gid + 8)) * DIM + col;
            *(uint32_t*)&g_Chi[i0] = h2bits(cacc[g][0], cacc[g][1]);
            *(uint32_t*)&g_Chi[i1] = h2bits(cacc[g][2], cacc[g][3]);
        }
    }

    // ---- final attn_weights write (mean over heads) ----
    {
        const float invh = 1.0f / NH;
#pragma unroll
        for (int rr = 0; rr < 4; rr++) {
            float* aw = attnw + ((size_t)(b * LQ + q0 + wid * 4 + rr)) * LKK + lane * 32;
#pragma unroll
            for (int j = 0; j < 8; j++) {
                float4 p = make_float4(awacc[rr][j*4] * invh,   awacc[rr][j*4+1] * invh,
                                       awacc[rr][j*4+2] * invh, awacc[rr][j*4+3] * invh);
                *(float4*)&aw[j * 4] = p;
            }
        }
    }
}

// ------------------------- layernorm -------------------------
__global__ __launch_bounds__(256) void ln_kernel(
    const float* __restrict__ X, const float* __restrict__ gam,
    const float* __restrict__ bet, float* __restrict__ out)
{
    __shared__ float red[64];
    __shared__ float s_mu, s_rinv;
    const int r = blockIdx.x, tid = threadIdx.x;
    const float* x = X + (size_t)r * DIM;
    float4 v = *(const float4*)&x[tid * 4];
    float s  = v.x + v.y + v.z + v.w;
    float sq = v.x * v.x + v.y * v.y + v.z * v.z + v.w * v.w;
#pragma unroll
    for (int o = 16; o > 0; o >>= 1) {
        s  += __shfl_xor_sync(0xffffffffu, s, o);
        sq += __shfl_xor_sync(0xffffffffu, sq, o);
    }
    const int w = tid >> 5;
    if ((tid & 31) == 0) { red[w] = s; red[32 + w] = sq; }
    __syncthreads();
    if (tid == 0) {
        float S = 0, Q = 0;
        for (int i = 0; i < 8; i++) { S += red[i]; Q += red[32 + i]; }
        float mu = S * (1.0f / DIM);
        float var = Q * (1.0f / DIM) - mu * mu;
        s_mu = mu;
        s_rinv = rsqrtf(var + EPSV);
    }
    __syncthreads();
    const float mu = s_mu, rinv = s_rinv;
    float4 gg = *(const float4*)&gam[tid * 4];
    float4 bb = *(const float4*)&bet[tid * 4];
    float4 o;
    o.x = (v.x - mu) * rinv * gg.x + bb.x;
    o.y = (v.y - mu) * rinv * gg.y + bb.y;
    o.z = (v.z - mu) * rinv * gg.z + bb.z;
    o.w = (v.w - mu) * rinv * gg.w + bb.w;
    *(float4*)&out[(size_t)r * DIM + tid * 4] = o;
}

// ------------------------- launch -------------------------
extern "C" void kernel_launch(void* const* d_in, const int* in_sizes, int n_in,
                              void* d_out, int out_size)
{
    const float* text   = (const float*)d_in[0];
    const float* vision = (const float*)d_in[1];
    const float* ipw    = (const float*)d_in[2];
    const float* ipb    = (const float*)d_in[3];
    const float* outw   = (const float*)d_in[4];
    const float* outb   = (const float*)d_in[5];
    const float* lng    = (const float*)d_in[6];
    const float* lnb    = (const float*)d_in[7];

    float* out   = (float*)d_out;
    float* attnw = out + (size_t)MQ * DIM;

    float* attp;
    cudaGetSymbolAddress((void**)&attp, g_att);

    __half *tAhi, *tVhi, *tWhi, *tOhi, *Qhi, *Khi, *Vhi, *Chi;
    cudaGetSymbolAddress((void**)&tAhi, g_tAhi);
    cudaGetSymbolAddress((void**)&tVhi, g_tVhi);
    cudaGetSymbolAddress((void**)&tWhi, g_tWhi);
    cudaGetSymbolAddress((void**)&tOhi, g_tOhi);
    cudaGetSymbolAddress((void**)&Qhi, g_Qhi);
    cudaGetSymbolAddress((void**)&Khi, g_Khi);
    cudaGetSymbolAddress((void**)&Vhi, g_Vhi);
    cudaGetSymbolAddress((void**)&Chi, g_Chi);

    cudaFuncSetAttribute(attn_mma, cudaFuncAttributeMaxDynamicSharedMemorySize, ATTN_SMEM);
    cudaFuncSetAttribute(gemm_mma<0>, cudaFuncAttributeMaxDynamicSharedMemorySize, GSM_TOTAL);
    cudaFuncSetAttribute(gemm_mma<1>, cudaFuncAttributeMaxDynamicSharedMemorySize, GSM_TOTAL);
    cudaFuncSetAttribute(gemm_mma<2>, cudaFuncAttributeMaxDynamicSharedMemorySize, GSM_TOTAL);

    int n4;
    n4 = (MQ * DIM) / 4;
    cvt_hi<<<(n4 + 255) / 256, 256>>>((const float4*)text, (uint32_t*)tAhi, 1.0f, n4);
    n4 = (MK * DIM) / 4;
    cvt_hi<<<(n4 + 255) / 256, 256>>>((const float4*)vision, (uint32_t*)tVhi, 1.0f, n4);
    n4 = (3 * DIM * DIM) / 4;
    cvt_hi<<<(n4 + 255) / 256, 256>>>((const float4*)ipw, (uint32_t*)tWhi, WUP, n4);
    n4 = (DIM * DIM) / 4;
    cvt_hi<<<(n4 + 255) / 256, 256>>>((const float4*)outw, (uint32_t*)tOhi, WUP, n4);

    // Q (scaled fp16) = 0.125*(text @ Wq^T + bq)
    gemm_mma<1><<<dim3(DIM / 128, MQ / 128), 256, GSM_TOTAL>>>(
        tAhi, tWhi, ipb, nullptr, nullptr, Qhi, nullptr, MQ, DIM, DIM);
    // [K|V] fp16 = vision @ [Wk|Wv]^T + [bk|bv]
    gemm_mma<2><<<dim3(2 * DIM / 128, MK / 128), 256, GSM_TOTAL>>>(
        tVhi, tWhi + (size_t)DIM * DIM, ipb + DIM, nullptr, nullptr, Khi, Vhi, MK, 2 * DIM, DIM);
    // attention
    attn_mma<<<NB * (LQ / 32), 256, ATTN_SMEM>>>(attnw);
    // attended = ctx @ out_w^T + out_b + text
    gemm_mma<0><<<dim3(DIM / 128, MQ / 128), 256, GSM_TOTAL>>>(
        Chi, tOhi, outb, text, attp, nullptr, nullptr, MQ, DIM, DIM);
    // layernorm
    ln_kernel<<<MQ, 256>>>(attp, lng, lnb, out);
}